// round 14
// baseline (speedup 1.0000x reference)
#include <cuda_runtime.h>
#include <cuda_bf16.h>
#include <math.h>
#include <stdint.h>

#define NB 20000
#define HD 256
#define NL 4
#define TWO_N (2*NB)
#define KTOT 768

// ---------------- device scratch ----------------
__device__ __nv_bfloat16 g_xh[(size_t)TWO_N * HD];          // h (bf16, sole copy)
__device__ __nv_bfloat16 g_Ys[(size_t)TWO_N * HD];          // neighbor sum (slim Y)
__device__ __nv_bfloat16 g_U [(size_t)TWO_N * HD];          // u (pre-LN), bf16
__device__ __nv_bfloat16 g_wth[(size_t)NL * 2 * HD * KTOT]; // W' hi [lh][n256][k768]
__device__ __nv_bfloat16 g_wtl[(size_t)NL * 2 * HD * KTOT]; // W' lo
__device__ float g_Cf [(size_t)NL * 2 * HD * HD];           // endpoint fixup (B2-Bh)U2/6
__device__ float g_Cf2[(size_t)NL * 2 * HD * HD];           // endpoint fixup A2U2/6
__device__ float g_bias [NL * 2 * HD];
__device__ float g_bias2[NL * 2 * HD];
__device__ float g_part[200 * HD];

// ---------------- helpers ----------------
__device__ __forceinline__ float gelu_exact(float x) {
    return 0.5f * x * (1.0f + erff(x * 0.70710678118654752f));
}
__device__ __forceinline__ float4 ld4(const float* p) { return *(const float4*)p; }
__device__ __forceinline__ float4 f4fma(float s, float4 a, float4 b) {
    return make_float4(fmaf(s,a.x,b.x), fmaf(s,a.y,b.y), fmaf(s,a.z,b.z), fmaf(s,a.w,b.w));
}
__device__ __forceinline__ float bflo(uint32_t u) { return __uint_as_float(u << 16); }
__device__ __forceinline__ float bfhi(uint32_t u) { return __uint_as_float(u & 0xffff0000u); }
__device__ __forceinline__ void unpack8(uint4 u, float* f) {
    f[0]=bflo(u.x); f[1]=bfhi(u.x); f[2]=bflo(u.y); f[3]=bfhi(u.y);
    f[4]=bflo(u.z); f[5]=bfhi(u.z); f[6]=bflo(u.w); f[7]=bfhi(u.w);
}
__device__ __forceinline__ uint32_t pk2(float a, float b) {
    __nv_bfloat162 t(__float2bfloat16(a), __float2bfloat16(b));
    return *(uint32_t*)&t;
}
__device__ __forceinline__ uint4 pack8(const float* f) {
    uint4 u;
    u.x = pk2(f[0],f[1]); u.y = pk2(f[2],f[3]);
    u.z = pk2(f[4],f[5]); u.w = pk2(f[6],f[7]);
    return u;
}
__device__ __forceinline__ uint32_t smem_u32(const void* p) {
    uint32_t a;
    asm("{ .reg .u64 t; cvta.to.shared.u64 t, %1; cvt.u32.u64 %0, t; }" : "=r"(a) : "l"(p));
    return a;
}
__device__ __forceinline__ void cpa16(uint32_t s, const void* g) {
    asm volatile("cp.async.cg.shared.global [%0], [%1], 16;" :: "r"(s), "l"(g));
}

#define MMA2(c, A, b0v, b1v) asm volatile( \
    "mma.sync.aligned.m16n8k16.row.col.f32.bf16.bf16.f32 " \
    "{%0,%1,%2,%3},{%4,%5,%6,%7},{%8,%9},{%0,%1,%2,%3};" \
    : "+f"(c[0]),"+f"(c[1]),"+f"(c[2]),"+f"(c[3]) \
    : "r"(A[0]),"r"(A[1]),"r"(A[2]),"r"(A[3]),"r"(b0v),"r"(b1v))

#define LDM4(r, addr) asm volatile( \
    "ldmatrix.sync.aligned.m8n8.x4.shared.b16 {%0,%1,%2,%3}, [%4];" \
    : "=r"((r)[0]),"=r"((r)[1]),"=r"((r)[2]),"=r"((r)[3]) : "r"(addr))

// ---------------- encode ----------------
__global__ void encode(const float* __restrict__ ex, const float* __restrict__ cx,
                       const float* __restrict__ Wew, const float* __restrict__ Web,
                       const float* __restrict__ Wcw, const float* __restrict__ Wcb) {
    int idx = blockIdx.x * blockDim.x + threadIdx.x;
    if (idx >= TWO_N * HD / 8) return;
    int c = (idx & 31) * 8;
    int g = idx >> 5;
    float f[8];
    if (g < NB) {
        const float* x = ex + (size_t)g * 5;
        float4 v0 = ld4(&Web[c]), v1 = ld4(&Web[c+4]);
        #pragma unroll
        for (int j = 0; j < 5; j++) {
            v0 = f4fma(x[j], ld4(&Wew[j * HD + c]),   v0);
            v1 = f4fma(x[j], ld4(&Wew[j * HD + c+4]), v1);
        }
        f[0]=v0.x; f[1]=v0.y; f[2]=v0.z; f[3]=v0.w; f[4]=v1.x; f[5]=v1.y; f[6]=v1.z; f[7]=v1.w;
    } else {
        const float* x = cx + (size_t)(g - NB) * 3;
        float4 v0 = ld4(&Wcb[c]), v1 = ld4(&Wcb[c+4]);
        #pragma unroll
        for (int j = 0; j < 3; j++) {
            v0 = f4fma(x[j], ld4(&Wcw[j * HD + c]),   v0);
            v1 = f4fma(x[j], ld4(&Wcw[j * HD + c+4]), v1);
        }
        f[0]=v0.x; f[1]=v0.y; f[2]=v0.z; f[3]=v0.w; f[4]=v1.x; f[5]=v1.y; f[6]=v1.z; f[7]=v1.w;
    }
    *(uint4*)&g_xh[(size_t)g * HD + c] = pack8(f);
}

// ---------------- weight folding ----------------
// sec0: S=U1+(2Bh+B2)U2/3 ; sec1: A_h U2/3 ; sec2: A2 U2/3 (-> W' bf16)
// sec3: Cf=(B2-Bh)U2/6 ; sec4: Cf2=A2 U2/6 (fp32). cb==10: bias folding.
__global__ __launch_bounds__(256, 2) void gemm_pre(const float* __restrict__ msg_w,
                                                   const float* __restrict__ upd_w,
                                                   const float* __restrict__ msg_b,
                                                   const float* __restrict__ upd_b) {
    int cb = blockIdx.x, rb = blockIdx.y, lh = blockIdx.z;
    int l = lh >> 1, h = lh & 1;

    __shared__ float As[2][16][132];
    __shared__ float Bs[2][16][128];
    int tid = threadIdx.x;

    if (cb == 10) {
        if (rb != 0) return;
        float* v1 = &As[0][0][0];
        float* v2 = v1 + HD;
        int c = tid;
        float mbh = msg_b[(l*3 + h)*HD + c];
        float mb2 = msg_b[(l*3 + 2)*HD + c];
        v1[c] = 2.f*mbh + mb2;
        v2[c] = mbh + mb2;
        __syncthreads();
        const float* U2 = upd_w + ((size_t)l*512 + HD) * HD;
        float s1 = 0.f, s2 = 0.f;
        for (int k = 0; k < HD; k++) {
            float u = U2[(size_t)k*HD + c];
            s1 += v1[k]*u; s2 += v2[k]*u;
        }
        g_bias [lh*HD + c] = s1*(1.f/3.f) + upd_b[l*HD + c];
        g_bias2[lh*HD + c] = s2*0.5f     + upd_b[l*HD + c];
        return;
    }

    int sec = cb >> 1;
    int col0 = (cb & 1) * 128;
    int row0 = rb * 128;
    const float* mh = msg_w + (size_t)(l*3 + h) * 512 * HD;
    const float* m2 = msg_w + (size_t)(l*3 + 2) * 512 * HD;
    const float* U1 = upd_w + (size_t)l * 512 * HD;
    const float* U2 = U1 + (size_t)HD * HD;
    const float* P1; const float* P2; float w1, w2, scale; int addU1;
    if (sec == 0)      { P1 = mh + HD*HD; w1 = 2.f; P2 = m2 + HD*HD; w2 = 1.f;  scale = 1.f/3.f; addU1 = 1; }
    else if (sec == 1) { P1 = mh;          w1 = 1.f; P2 = 0;          w2 = 0.f;  scale = 1.f/3.f; addU1 = 0; }
    else if (sec == 2) { P1 = m2;          w1 = 1.f; P2 = 0;          w2 = 0.f;  scale = 1.f/3.f; addU1 = 0; }
    else if (sec == 3) { P1 = m2 + HD*HD; w1 = 1.f; P2 = mh + HD*HD; w2 = -1.f; scale = 1.f/6.f; addU1 = 0; }
    else               { P1 = m2;          w1 = 1.f; P2 = 0;          w2 = 0.f;  scale = 1.f/6.f; addU1 = 0; }

    int tx = tid & 15, ty = tid >> 4;
    int ar = tid >> 2, ak = (tid & 3) * 4;
    int bk = tid >> 5, bn = (tid & 31) * 4;

    float acc[8][8];
    #pragma unroll
    for (int i = 0; i < 8; i++)
        #pragma unroll
        for (int j = 0; j < 8; j++) acc[i][j] = 0.f;

    float4 a0v, a1v, b0v, b1v;
    {
        int r0 = row0 + ar, r1 = row0 + ar + 64;
        a0v = ld4(&P1[(size_t)r0*HD + ak]);
        a1v = ld4(&P1[(size_t)r1*HD + ak]);
        if (P2) { a0v = f4fma(w2/w1, ld4(&P2[(size_t)r0*HD + ak]), a0v);
                  a1v = f4fma(w2/w1, ld4(&P2[(size_t)r1*HD + ak]), a1v); }
        b0v = ld4(&U2[(size_t)bk*HD + col0 + bn]);
        b1v = ld4(&U2[(size_t)(bk+8)*HD + col0 + bn]);
    }
    As[0][ak+0][ar]=a0v.x; As[0][ak+1][ar]=a0v.y; As[0][ak+2][ar]=a0v.z; As[0][ak+3][ar]=a0v.w;
    As[0][ak+0][64+ar]=a1v.x; As[0][ak+1][64+ar]=a1v.y; As[0][ak+2][64+ar]=a1v.z; As[0][ak+3][64+ar]=a1v.w;
    *(float4*)&Bs[0][bk][bn] = b0v; *(float4*)&Bs[0][bk+8][bn] = b1v;
    __syncthreads();

    int buf = 0;
    #pragma unroll 1
    for (int t = 0; t < 16; t++) {
        if (t < 15) {
            int k0 = (t + 1) * 16;
            int r0 = row0 + ar, r1 = row0 + ar + 64;
            a0v = ld4(&P1[(size_t)r0*HD + k0 + ak]);
            a1v = ld4(&P1[(size_t)r1*HD + k0 + ak]);
            if (P2) { a0v = f4fma(w2/w1, ld4(&P2[(size_t)r0*HD + k0 + ak]), a0v);
                      a1v = f4fma(w2/w1, ld4(&P2[(size_t)r1*HD + k0 + ak]), a1v); }
            b0v = ld4(&U2[(size_t)(k0+bk)*HD + col0 + bn]);
            b1v = ld4(&U2[(size_t)(k0+bk+8)*HD + col0 + bn]);
        }
        #pragma unroll
        for (int k = 0; k < 16; k++) {
            float4 pa0 = *(float4*)&As[buf][k][ty*4];
            float4 pa1 = *(float4*)&As[buf][k][64 + ty*4];
            float4 pb0 = *(float4*)&Bs[buf][k][tx*4];
            float4 pb1 = *(float4*)&Bs[buf][k][64 + tx*4];
            float aa[8] = {pa0.x,pa0.y,pa0.z,pa0.w,pa1.x,pa1.y,pa1.z,pa1.w};
            float bb[8] = {pb0.x,pb0.y,pb0.z,pb0.w,pb1.x,pb1.y,pb1.z,pb1.w};
            #pragma unroll
            for (int i = 0; i < 8; i++)
                #pragma unroll
                for (int j = 0; j < 8; j++)
                    acc[i][j] = fmaf(aa[i], bb[j], acc[i][j]);
        }
        if (t < 15) {
            int nb2 = buf ^ 1;
            As[nb2][ak+0][ar]=a0v.x; As[nb2][ak+1][ar]=a0v.y; As[nb2][ak+2][ar]=a0v.z; As[nb2][ak+3][ar]=a0v.w;
            As[nb2][ak+0][64+ar]=a1v.x; As[nb2][ak+1][64+ar]=a1v.y; As[nb2][ak+2][64+ar]=a1v.z; As[nb2][ak+3][64+ar]=a1v.w;
            *(float4*)&Bs[nb2][bk][bn] = b0v; *(float4*)&Bs[nb2][bk+8][bn] = b1v;
        }
        __syncthreads();
        buf ^= 1;
    }

    float sc = w1 * scale;
    #pragma unroll
    for (int ih = 0; ih < 2; ih++)
        #pragma unroll
        for (int ii = 0; ii < 4; ii++) {
            int r = row0 + ih*64 + ty*4 + ii;          // k index (0..255)
            #pragma unroll
            for (int jh = 0; jh < 2; jh++) {
                int c = col0 + jh*64 + tx*4;           // n index (0..255)
                float vv[4];
                #pragma unroll
                for (int j = 0; j < 4; j++) vv[j] = acc[ih*4+ii][jh*4+j] * sc;
                if (addU1) {
                    float4 u = ld4(&U1[(size_t)r*HD + c]);
                    vv[0]+=u.x; vv[1]+=u.y; vv[2]+=u.z; vv[3]+=u.w;
                }
                if (sec < 3) {
                    #pragma unroll
                    for (int j = 0; j < 4; j++) {
                        size_t o = ((size_t)lh*HD + (c + j))*KTOT + sec*HD + r;
                        __nv_bfloat16 hi = __float2bfloat16(vv[j]);
                        g_wth[o] = hi;
                        g_wtl[o] = __float2bfloat16(vv[j] - __bfloat162float(hi));
                    }
                } else {
                    float* dst = (sec == 3) ? g_Cf : g_Cf2;
                    float4 v = make_float4(vv[0],vv[1],vv[2],vv[3]);
                    *(float4*)&dst[(size_t)lh*HD*HD + (size_t)r*HD + c] = v;
                }
            }
        }
}

// ---------------- buildY: Ys[n] = x(n-1)+x(n+1)  (1.5x at endpoints) -----
__global__ __launch_bounds__(256) void buildY() {
    int node = blockIdx.x * 8 + (threadIdx.x >> 5);
    int lane = threadIdx.x & 31;
    int half = node >= NB ? 1 : 0;
    int i = node - half * NB;
    int c = lane * 8;
    float f[8] = {0.f,0.f,0.f,0.f,0.f,0.f,0.f,0.f};
    if (i > 0) {
        float a[8]; unpack8(*(const uint4*)&g_xh[(size_t)(node-1)*HD + c], a);
        #pragma unroll
        for (int j = 0; j < 8; j++) f[j] += a[j];
    }
    if (i < NB - 1) {
        float a[8]; unpack8(*(const uint4*)&g_xh[(size_t)(node+1)*HD + c], a);
        #pragma unroll
        for (int j = 0; j < 8; j++) f[j] += a[j];
    }
    if (i == 0 || i == NB - 1) {
        #pragma unroll
        for (int j = 0; j < 8; j++) f[j] *= 1.5f;
    }
    *(uint4*)&g_Ys[(size_t)node*HD + c] = pack8(f);
}

// ---------------- tensor-core GEMM: u = [x|Ys|xp] @ W'^T (K=768) ---------
#define MAT_SZ  10240            // 128 rows * 80 B
#define STG_TOT 30720            // AH | BH | BL
#define SMEM_MMA 67584

__global__ __launch_bounds__(256, 2) void gemm_mma(int l) {
    extern __shared__ __align__(16) char sm[];
    uint32_t sb = smem_u32(sm);
    int tid = threadIdx.x, wid = tid >> 5, lane = tid & 31;
    int cb = blockIdx.x, rb = blockIdx.y, half = blockIdx.z;
    int lh = l*2 + half;
    const __nv_bfloat16* Bwh = g_wth + (size_t)lh*HD*KTOT;
    const __nv_bfloat16* Bwl = g_wtl + (size_t)lh*HD*KTOT;

    int lr0 = tid >> 2, lseg = tid & 3;
    int r0 = rb*128 + lr0;      if (r0 >= NB) r0 = NB-1;
    int r1 = rb*128 + lr0 + 64; if (r1 >= NB) r1 = NB-1;
    size_t aS0 = (size_t)(half*NB + r0) * HD,     aS1 = (size_t)(half*NB + r1) * HD;
    size_t aP0 = (size_t)((1-half)*NB + r0) * HD, aP1 = (size_t)((1-half)*NB + r1) * HD;
    size_t bn0 = (size_t)(cb*128 + lr0) * KTOT;
    size_t bn1 = (size_t)(cb*128 + lr0 + 64) * KTOT;

    #define LOAD_STAGE(s, k0) do {                                             \
        uint32_t d0 = sb + (uint32_t)(s)*STG_TOT + lr0*80 + lseg*16;           \
        uint32_t d1 = d0 + 64*80;                                              \
        int sec_ = (k0) >> 8;                                                  \
        size_t kc = (size_t)((k0) & 255) + lseg*8;                             \
        const __nv_bfloat16* Ab = (sec_ == 1) ? g_Ys : g_xh;                   \
        size_t ra0 = (sec_ == 2) ? aP0 : aS0;                                  \
        size_t ra1 = (sec_ == 2) ? aP1 : aS1;                                  \
        cpa16(d0,            Ab + ra0 + kc);                                   \
        cpa16(d1,            Ab + ra1 + kc);                                   \
        size_t kb = (size_t)(k0) + lseg*8;                                     \
        cpa16(d0 + MAT_SZ,   Bwh + bn0 + kb);                                  \
        cpa16(d1 + MAT_SZ,   Bwh + bn1 + kb);                                  \
        cpa16(d0 + 2*MAT_SZ, Bwl + bn0 + kb);                                  \
        cpa16(d1 + 2*MAT_SZ, Bwl + bn1 + kb);                                  \
        asm volatile("cp.async.commit_group;" ::: "memory");                   \
    } while (0)

    float acc[4][4][4];
    #pragma unroll
    for (int i = 0; i < 4; i++)
        #pragma unroll
        for (int j = 0; j < 4; j++)
            #pragma unroll
            for (int q = 0; q < 4; q++) acc[i][j][q] = 0.f;

    LOAD_STAGE(0, 0);
    LOAD_STAGE(1, 32);

    int warp_m = (wid >> 2) * 64, warp_n = (wid & 3) * 32;
    int la7 = lane & 7, lb8 = (lane >> 3) & 1, lhi = lane >> 4;
    uint32_t aoff = (uint32_t)(warp_m + la7 + lb8*8)*80 + lhi*16;
    uint32_t boff = MAT_SZ + (uint32_t)(warp_n + lhi*8 + la7)*80 + lb8*16;

    #pragma unroll 1
    for (int kt = 0; kt < 24; kt++) {
        if (kt < 23) asm volatile("cp.async.wait_group 1;" ::: "memory");
        else         asm volatile("cp.async.wait_group 0;" ::: "memory");
        __syncthreads();
        uint32_t stg = sb + (uint32_t)(kt & 1) * STG_TOT;
        #pragma unroll
        for (int k16 = 0; k16 < 2; k16++) {
            uint32_t ko = k16 * 32;
            uint32_t ah[4][4];
            #pragma unroll
            for (int i = 0; i < 4; i++)
                LDM4(ah[i], stg + aoff + i*1280 + ko);
            #pragma unroll
            for (int jj = 0; jj < 2; jj++) {
                uint32_t bh[4], bl[4];
                LDM4(bh, stg + boff + jj*1280 + ko);
                LDM4(bl, stg + MAT_SZ + boff + jj*1280 + ko);
                #pragma unroll
                for (int j2 = 0; j2 < 2; j2++) {
                    int j = jj*2 + j2;
                    #pragma unroll
                    for (int i = 0; i < 4; i++) {
                        MMA2(acc[i][j], ah[i], bh[j2*2], bh[j2*2+1]);
                        MMA2(acc[i][j], ah[i], bl[j2*2], bl[j2*2+1]);
                    }
                }
            }
        }
        __syncthreads();
        if (kt + 2 < 24) LOAD_STAGE(kt & 1, (kt + 2) * 32);
    }

    asm volatile("cp.async.wait_group 0;" ::: "memory");
    __syncthreads();
    float* Cs = (float*)sm;                    // 128 x 132 floats
    int g = lane >> 2;
    int ct = (lane & 3) * 2;
    #pragma unroll
    for (int i = 0; i < 4; i++)
        #pragma unroll
        for (int j = 0; j < 4; j++) {
            int r = warp_m + i*16 + g;
            int c = warp_n + j*8 + ct;
            *(float2*)&Cs[(size_t)r*132 + c]      = make_float2(acc[i][j][0], acc[i][j][1]);
            *(float2*)&Cs[(size_t)(r+8)*132 + c]  = make_float2(acc[i][j][2], acc[i][j][3]);
        }
    __syncthreads();
    #pragma unroll
    for (int it = 0; it < 16; it++) {
        int idx = tid + it*256;
        int r = idx >> 5, c4 = (idx & 31) * 4;
        int node = rb*128 + r;
        if (node < NB) {
            float4 v = *(float4*)&Cs[(size_t)r*132 + c4];
            uint2 pk;
            pk.x = pk2(v.x, v.y); pk.y = pk2(v.z, v.w);
            *(uint2*)&g_U[((size_t)(half*NB + node))*HD + cb*128 + c4] = pk;
        }
    }
    #undef LOAD_STAGE
}

// ---------------- ep_fix: g_U[ep] += Cf@x + Cf2@xp + (bias2 - bias) ------
// 32 blocks: 4 nodes x 8 col-chunks; 256 thr = 32 cols x 8 k-groups.
__global__ void ep_fix(int l) {
    int e  = blockIdx.x >> 3;
    int cc = blockIdx.x & 7;
    int half = e >> 1;
    int i = (e & 1) ? NB - 1 : 0;
    int node = half * NB + i;
    int pnode = half ? node - NB : node + NB;
    int lh = l*2 + half;
    int tid = threadIdx.x;
    int col = cc*32 + (tid & 31);
    int kg  = tid >> 5;

    __shared__ float xs[HD], xp[HD];
    __shared__ float red[8][33];
    xs[tid] = __bfloat162float(g_xh[(size_t)node*HD + tid]);
    xp[tid] = __bfloat162float(g_xh[(size_t)pnode*HD + tid]);
    __syncthreads();

    const float* Cf  = g_Cf  + (size_t)lh*HD*HD;
    const float* Cf2 = g_Cf2 + (size_t)lh*HD*HD;
    float p = 0.f;
    #pragma unroll 8
    for (int k = kg*32; k < kg*32 + 32; k++) {
        p = fmaf(xs[k], Cf [(size_t)k*HD + col], p);
        p = fmaf(xp[k], Cf2[(size_t)k*HD + col], p);
    }
    red[kg][tid & 31] = p;
    __syncthreads();
    if (kg == 0) {
        float s = 0.f;
        #pragma unroll
        for (int w = 0; w < 8; w++) s += red[w][tid & 31];
        size_t o = (size_t)node*HD + col;
        float u = __bfloat162float(g_U[o]) + s
                + g_bias2[lh*HD + col] - g_bias[lh*HD + col];
        g_U[o] = __float2bfloat16(u);
    }
}

// ---------------- combine2: LN + GeLU + residual (ALL nodes) -------------
__global__ __launch_bounds__(256) void combine2(int l,
        const float* __restrict__ ln_g, const float* __restrict__ ln_b) {
    int node = blockIdx.x * 8 + (threadIdx.x >> 5);
    int lane = threadIdx.x & 31;
    int half = node >= NB ? 1 : 0;
    int c = lane * 8;

    float u[8];
    unpack8(*(const uint4*)&g_U[(size_t)node*HD + c], u);
    const float* bi = g_bias + (l*2 + half) * HD;
    float4 bi0 = ld4(bi + c), bi1 = ld4(bi + c + 4);
    u[0]+=bi0.x; u[1]+=bi0.y; u[2]+=bi0.z; u[3]+=bi0.w;
    u[4]+=bi1.x; u[5]+=bi1.y; u[6]+=bi1.z; u[7]+=bi1.w;

    float s = 0.f, q = 0.f;
    #pragma unroll
    for (int j = 0; j < 8; j++) { s += u[j]; q = fmaf(u[j], u[j], q); }
    #pragma unroll
    for (int off = 16; off; off >>= 1) {
        s += __shfl_xor_sync(0xffffffff, s, off);
        q += __shfl_xor_sync(0xffffffff, q, off);
    }
    float mu = s * (1.f/HD);
    float rs = rsqrtf(q * (1.f/HD) - mu*mu + 1e-5f);

    float4 g0 = ld4(ln_g + l*HD + c), g1 = ld4(ln_g + l*HD + c + 4);
    float4 b0 = ld4(ln_b + l*HD + c), b1 = ld4(ln_b + l*HD + c + 4);
    float gg[8] = {g0.x,g0.y,g0.z,g0.w,g1.x,g1.y,g1.z,g1.w};
    float bb[8] = {b0.x,b0.y,b0.z,b0.w,b1.x,b1.y,b1.z,b1.w};

    float x8[8];
    unpack8(*(const uint4*)&g_xh[(size_t)node*HD + c], x8);
    #pragma unroll
    for (int j = 0; j < 8; j++)
        x8[j] += gelu_exact((u[j] - mu) * rs * gg[j] + bb[j]);
    *(uint4*)&g_xh[(size_t)node*HD + c] = pack8(x8);
}

// ---------------- readout ----------------
__global__ void colmean() {
    int c = threadIdx.x;
    int r0 = blockIdx.x * 100;
    float s = 0.f;
    for (int r = r0; r < r0 + 100; r++)
        s += __bfloat162float(g_xh[(size_t)r * HD + c]);
    g_part[blockIdx.x * HD + c] = s;
}

__global__ void decoder(const float* __restrict__ dec1_w, const float* __restrict__ dec1_b,
                        const float* __restrict__ dec2_w, const float* __restrict__ dec2_b,
                        const float* __restrict__ Kp, const float* __restrict__ tau,
                        const float* __restrict__ tau_max, const float* __restrict__ lam,
                        float* __restrict__ out) {
    __shared__ float hm[HD], z[HD], red[64];
    int t = threadIdx.x;
    float acc0 = 0.f;
    for (int b = 0; b < 200; b++) acc0 += g_part[b * HD + t];
    hm[t] = acc0 * (1.0f / NB);
    __syncthreads();
    float acc = dec1_b[t];
    for (int k = 0; k < HD; k++) acc += hm[k] * dec1_w[k * HD + t];
    z[t] = gelu_exact(acc);
    __syncthreads();
    if (t < 128) {
        float a = dec2_b[t];
        for (int k = 0; k < HD; k++) a += z[k] * dec2_w[k * 128 + t];
        out[t] = a;
    }
    if (t < 64) {
        red[t] = Kp[t] * tau[t] / tau_max[t];
        out[129 + t] = Kp[t];
    }
    __syncthreads();
    if (t == 0) {
        float s = 0.f;
        for (int i = 0; i < 64; i++) s += red[i];
        out[128] = fabsf(lam[0]) - s;
    }
}

// ---------------- launch ----------------
extern "C" void kernel_launch(void* const* d_in, const int* in_sizes, int n_in,
                              void* d_out, int out_size) {
    const float* energy_x     = (const float*)d_in[0];
    const float* comm_x       = (const float*)d_in[1];
    const float* tau          = (const float*)d_in[2];
    const float* tau_max      = (const float*)d_in[3];
    const float* lambda_min_0 = (const float*)d_in[4];
    const float* We_w         = (const float*)d_in[5];
    const float* We_b         = (const float*)d_in[6];
    const float* Wc_w         = (const float*)d_in[7];
    const float* Wc_b         = (const float*)d_in[8];
    const float* msg_w        = (const float*)d_in[9];
    const float* msg_b        = (const float*)d_in[10];
    const float* upd_w        = (const float*)d_in[11];
    const float* upd_b        = (const float*)d_in[12];
    const float* ln_g         = (const float*)d_in[13];
    const float* ln_b         = (const float*)d_in[14];
    const float* dec1_w       = (const float*)d_in[15];
    const float* dec1_b       = (const float*)d_in[16];
    const float* dec2_w       = (const float*)d_in[17];
    const float* dec2_b       = (const float*)d_in[18];
    const float* K_param      = (const float*)d_in[19];
    float* out = (float*)d_out;

    cudaFuncSetAttribute(gemm_mma, cudaFuncAttributeMaxDynamicSharedMemorySize, SMEM_MMA);

    gemm_pre<<<dim3(11, 2, 8), 256>>>(msg_w, upd_w, msg_b, upd_b);
    encode<<<(TWO_N * HD / 8 + 255) / 256, 256>>>(energy_x, comm_x, We_w, We_b, Wc_w, Wc_b);

    for (int l = 0; l < NL; l++) {
        buildY<<<TWO_N / 8, 256>>>();
        gemm_mma<<<dim3(2, (NB + 127) / 128, 2), 256, SMEM_MMA>>>(l);
        ep_fix<<<32, 256>>>(l);
        combine2<<<TWO_N / 8, 256>>>(l, ln_g, ln_b);
    }

    colmean<<<200, 256>>>();
    decoder<<<1, 256>>>(dec1_w, dec1_b, dec2_w, dec2_b,
                        K_param, tau, tau_max, lambda_min_0, out);
}

// round 15
// speedup vs baseline: 1.0794x; 1.0794x over previous
#include <cuda_runtime.h>
#include <cuda_bf16.h>
#include <math.h>
#include <stdint.h>

#define NB 20000
#define HD 256
#define NL 4
#define TWO_N (2*NB)
#define KTOT 768

// ---------------- device scratch ----------------
__device__ __nv_bfloat16 g_xh[(size_t)TWO_N * HD];          // h (bf16, sole copy)
__device__ __nv_bfloat16 g_Y [(size_t)TWO_N * KTOT];        // [x | nbr-sum | x(p)]
__device__ __nv_bfloat16 g_U [(size_t)TWO_N * HD];          // u (pre-LN), bf16
__device__ __nv_bfloat16 g_wth[(size_t)NL * 2 * HD * KTOT]; // W' hi [lh][n256][k768]
__device__ __nv_bfloat16 g_wtl[(size_t)NL * 2 * HD * KTOT]; // W' lo
__device__ float g_Cf [(size_t)NL * 2 * HD * HD];           // endpoint fixup (B2-Bh)U2/6
__device__ float g_bias [NL * 2 * HD];
__device__ float g_bias2[NL * 2 * HD];
__device__ float g_part[200 * HD];

// ---------------- helpers ----------------
__device__ __forceinline__ float gelu_exact(float x) {
    return 0.5f * x * (1.0f + erff(x * 0.70710678118654752f));
}
__device__ __forceinline__ float4 ld4(const float* p) { return *(const float4*)p; }
__device__ __forceinline__ float4 f4fma(float s, float4 a, float4 b) {
    return make_float4(fmaf(s,a.x,b.x), fmaf(s,a.y,b.y), fmaf(s,a.z,b.z), fmaf(s,a.w,b.w));
}
__device__ __forceinline__ float bflo(uint32_t u) { return __uint_as_float(u << 16); }
__device__ __forceinline__ float bfhi(uint32_t u) { return __uint_as_float(u & 0xffff0000u); }
__device__ __forceinline__ void unpack8(uint4 u, float* f) {
    f[0]=bflo(u.x); f[1]=bfhi(u.x); f[2]=bflo(u.y); f[3]=bfhi(u.y);
    f[4]=bflo(u.z); f[5]=bfhi(u.z); f[6]=bflo(u.w); f[7]=bfhi(u.w);
}
__device__ __forceinline__ uint32_t pk2(float a, float b) {
    __nv_bfloat162 t(__float2bfloat16(a), __float2bfloat16(b));
    return *(uint32_t*)&t;
}
__device__ __forceinline__ uint4 pack8(const float* f) {
    uint4 u;
    u.x = pk2(f[0],f[1]); u.y = pk2(f[2],f[3]);
    u.z = pk2(f[4],f[5]); u.w = pk2(f[6],f[7]);
    return u;
}
__device__ __forceinline__ uint32_t smem_u32(const void* p) {
    uint32_t a;
    asm("{ .reg .u64 t; cvta.to.shared.u64 t, %1; cvt.u32.u64 %0, t; }" : "=r"(a) : "l"(p));
    return a;
}
__device__ __forceinline__ void cpa16(uint32_t s, const void* g) {
    asm volatile("cp.async.cg.shared.global [%0], [%1], 16;" :: "r"(s), "l"(g));
}

#define MMA2(c, A, b0v, b1v) asm volatile( \
    "mma.sync.aligned.m16n8k16.row.col.f32.bf16.bf16.f32 " \
    "{%0,%1,%2,%3},{%4,%5,%6,%7},{%8,%9},{%0,%1,%2,%3};" \
    : "+f"(c[0]),"+f"(c[1]),"+f"(c[2]),"+f"(c[3]) \
    : "r"(A[0]),"r"(A[1]),"r"(A[2]),"r"(A[3]),"r"(b0v),"r"(b1v))

#define LDM4(r, addr) asm volatile( \
    "ldmatrix.sync.aligned.m8n8.x4.shared.b16 {%0,%1,%2,%3}, [%4];" \
    : "=r"((r)[0]),"=r"((r)[1]),"=r"((r)[2]),"=r"((r)[3]) : "r"(addr))

// ---------------- encode: x -> g_xh, g_Y sec0, g_Y[partner] sec2 ---------
__global__ void encode(const float* __restrict__ ex, const float* __restrict__ cx,
                       const float* __restrict__ Wew, const float* __restrict__ Web,
                       const float* __restrict__ Wcw, const float* __restrict__ Wcb) {
    int idx = blockIdx.x * blockDim.x + threadIdx.x;
    if (idx >= TWO_N * HD / 8) return;
    int c = (idx & 31) * 8;
    int g = idx >> 5;
    float f[8];
    if (g < NB) {
        const float* x = ex + (size_t)g * 5;
        float4 v0 = ld4(&Web[c]), v1 = ld4(&Web[c+4]);
        #pragma unroll
        for (int j = 0; j < 5; j++) {
            v0 = f4fma(x[j], ld4(&Wew[j * HD + c]),   v0);
            v1 = f4fma(x[j], ld4(&Wew[j * HD + c+4]), v1);
        }
        f[0]=v0.x; f[1]=v0.y; f[2]=v0.z; f[3]=v0.w; f[4]=v1.x; f[5]=v1.y; f[6]=v1.z; f[7]=v1.w;
    } else {
        const float* x = cx + (size_t)(g - NB) * 3;
        float4 v0 = ld4(&Wcb[c]), v1 = ld4(&Wcb[c+4]);
        #pragma unroll
        for (int j = 0; j < 3; j++) {
            v0 = f4fma(x[j], ld4(&Wcw[j * HD + c]),   v0);
            v1 = f4fma(x[j], ld4(&Wcw[j * HD + c+4]), v1);
        }
        f[0]=v0.x; f[1]=v0.y; f[2]=v0.z; f[3]=v0.w; f[4]=v1.x; f[5]=v1.y; f[6]=v1.z; f[7]=v1.w;
    }
    uint4 pk = pack8(f);
    *(uint4*)&g_xh[(size_t)g * HD + c] = pk;
    *(uint4*)&g_Y[(size_t)g * KTOT + c] = pk;                 // sec0
    int half = g >= NB ? 1 : 0;
    int i = g - half * NB;
    int p = half ? g - NB : g + NB;
    uint4 pk2v = pk;
    if (i == 0 || i == NB - 1) {                              // p is endpoint too
        float s[8];
        #pragma unroll
        for (int j = 0; j < 8; j++) s[j] = f[j] * 1.5f;
        pk2v = pack8(s);
    }
    *(uint4*)&g_Y[(size_t)p * KTOT + 512 + c] = pk2v;         // sec2 of partner
}

// ---------------- weight folding ----------------
// sec0: S=U1+(2Bh+B2)U2/3 ; sec1: A_h U2/3 ; sec2: A2 U2/3 (-> W' bf16)
// sec3: Cf=(B2-Bh)U2/6 (fp32). cb==8: bias folding.
__global__ __launch_bounds__(256, 2) void gemm_pre(const float* __restrict__ msg_w,
                                                   const float* __restrict__ upd_w,
                                                   const float* __restrict__ msg_b,
                                                   const float* __restrict__ upd_b) {
    int cb = blockIdx.x, rb = blockIdx.y, lh = blockIdx.z;
    int l = lh >> 1, h = lh & 1;

    __shared__ float As[2][16][132];
    __shared__ float Bs[2][16][128];
    int tid = threadIdx.x;

    if (cb == 8) {
        if (rb != 0) return;
        float* v1 = &As[0][0][0];
        float* v2 = v1 + HD;
        int c = tid;
        float mbh = msg_b[(l*3 + h)*HD + c];
        float mb2 = msg_b[(l*3 + 2)*HD + c];
        v1[c] = 2.f*mbh + mb2;
        v2[c] = mbh + mb2;
        __syncthreads();
        const float* U2 = upd_w + ((size_t)l*512 + HD) * HD;
        float s1 = 0.f, s2 = 0.f;
        for (int k = 0; k < HD; k++) {
            float u = U2[(size_t)k*HD + c];
            s1 += v1[k]*u; s2 += v2[k]*u;
        }
        g_bias [lh*HD + c] = s1*(1.f/3.f) + upd_b[l*HD + c];
        g_bias2[lh*HD + c] = s2*0.5f     + upd_b[l*HD + c];
        return;
    }

    int sec = cb >> 1;
    int col0 = (cb & 1) * 128;
    int row0 = rb * 128;
    const float* mh = msg_w + (size_t)(l*3 + h) * 512 * HD;
    const float* m2 = msg_w + (size_t)(l*3 + 2) * 512 * HD;
    const float* U1 = upd_w + (size_t)l * 512 * HD;
    const float* U2 = U1 + (size_t)HD * HD;
    const float* P1; const float* P2; float w1, w2, scale; int addU1;
    if (sec == 0)      { P1 = mh + HD*HD; w1 = 2.f; P2 = m2 + HD*HD; w2 = 1.f;  scale = 1.f/3.f; addU1 = 1; }
    else if (sec == 1) { P1 = mh;          w1 = 1.f; P2 = 0;          w2 = 0.f;  scale = 1.f/3.f; addU1 = 0; }
    else if (sec == 2) { P1 = m2;          w1 = 1.f; P2 = 0;          w2 = 0.f;  scale = 1.f/3.f; addU1 = 0; }
    else               { P1 = m2 + HD*HD; w1 = 1.f; P2 = mh + HD*HD; w2 = -1.f; scale = 1.f/6.f; addU1 = 0; }

    int tx = tid & 15, ty = tid >> 4;
    int ar = tid >> 2, ak = (tid & 3) * 4;
    int bk = tid >> 5, bn = (tid & 31) * 4;

    float acc[8][8];
    #pragma unroll
    for (int i = 0; i < 8; i++)
        #pragma unroll
        for (int j = 0; j < 8; j++) acc[i][j] = 0.f;

    float4 a0v, a1v, b0v, b1v;
    {
        int r0 = row0 + ar, r1 = row0 + ar + 64;
        a0v = ld4(&P1[(size_t)r0*HD + ak]);
        a1v = ld4(&P1[(size_t)r1*HD + ak]);
        if (P2) { a0v = f4fma(w2/w1, ld4(&P2[(size_t)r0*HD + ak]), a0v);
                  a1v = f4fma(w2/w1, ld4(&P2[(size_t)r1*HD + ak]), a1v); }
        b0v = ld4(&U2[(size_t)bk*HD + col0 + bn]);
        b1v = ld4(&U2[(size_t)(bk+8)*HD + col0 + bn]);
    }
    As[0][ak+0][ar]=a0v.x; As[0][ak+1][ar]=a0v.y; As[0][ak+2][ar]=a0v.z; As[0][ak+3][ar]=a0v.w;
    As[0][ak+0][64+ar]=a1v.x; As[0][ak+1][64+ar]=a1v.y; As[0][ak+2][64+ar]=a1v.z; As[0][ak+3][64+ar]=a1v.w;
    *(float4*)&Bs[0][bk][bn] = b0v; *(float4*)&Bs[0][bk+8][bn] = b1v;
    __syncthreads();

    int buf = 0;
    #pragma unroll 1
    for (int t = 0; t < 16; t++) {
        if (t < 15) {
            int k0 = (t + 1) * 16;
            int r0 = row0 + ar, r1 = row0 + ar + 64;
            a0v = ld4(&P1[(size_t)r0*HD + k0 + ak]);
            a1v = ld4(&P1[(size_t)r1*HD + k0 + ak]);
            if (P2) { a0v = f4fma(w2/w1, ld4(&P2[(size_t)r0*HD + k0 + ak]), a0v);
                      a1v = f4fma(w2/w1, ld4(&P2[(size_t)r1*HD + k0 + ak]), a1v); }
            b0v = ld4(&U2[(size_t)(k0+bk)*HD + col0 + bn]);
            b1v = ld4(&U2[(size_t)(k0+bk+8)*HD + col0 + bn]);
        }
        #pragma unroll
        for (int k = 0; k < 16; k++) {
            float4 pa0 = *(float4*)&As[buf][k][ty*4];
            float4 pa1 = *(float4*)&As[buf][k][64 + ty*4];
            float4 pb0 = *(float4*)&Bs[buf][k][tx*4];
            float4 pb1 = *(float4*)&Bs[buf][k][64 + tx*4];
            float aa[8] = {pa0.x,pa0.y,pa0.z,pa0.w,pa1.x,pa1.y,pa1.z,pa1.w};
            float bb[8] = {pb0.x,pb0.y,pb0.z,pb0.w,pb1.x,pb1.y,pb1.z,pb1.w};
            #pragma unroll
            for (int i = 0; i < 8; i++)
                #pragma unroll
                for (int j = 0; j < 8; j++)
                    acc[i][j] = fmaf(aa[i], bb[j], acc[i][j]);
        }
        if (t < 15) {
            int nb2 = buf ^ 1;
            As[nb2][ak+0][ar]=a0v.x; As[nb2][ak+1][ar]=a0v.y; As[nb2][ak+2][ar]=a0v.z; As[nb2][ak+3][ar]=a0v.w;
            As[nb2][ak+0][64+ar]=a1v.x; As[nb2][ak+1][64+ar]=a1v.y; As[nb2][ak+2][64+ar]=a1v.z; As[nb2][ak+3][64+ar]=a1v.w;
            *(float4*)&Bs[nb2][bk][bn] = b0v; *(float4*)&Bs[nb2][bk+8][bn] = b1v;
        }
        __syncthreads();
        buf ^= 1;
    }

    float sc = w1 * scale;
    #pragma unroll
    for (int ih = 0; ih < 2; ih++)
        #pragma unroll
        for (int ii = 0; ii < 4; ii++) {
            int r = row0 + ih*64 + ty*4 + ii;          // k index (0..255)
            #pragma unroll
            for (int jh = 0; jh < 2; jh++) {
                int c = col0 + jh*64 + tx*4;           // n index (0..255)
                float vv[4];
                #pragma unroll
                for (int j = 0; j < 4; j++) vv[j] = acc[ih*4+ii][jh*4+j] * sc;
                if (addU1) {
                    float4 u = ld4(&U1[(size_t)r*HD + c]);
                    vv[0]+=u.x; vv[1]+=u.y; vv[2]+=u.z; vv[3]+=u.w;
                }
                if (sec < 3) {
                    #pragma unroll
                    for (int j = 0; j < 4; j++) {
                        size_t o = ((size_t)lh*HD + (c + j))*KTOT + sec*HD + r;
                        __nv_bfloat16 hi = __float2bfloat16(vv[j]);
                        g_wth[o] = hi;
                        g_wtl[o] = __float2bfloat16(vv[j] - __bfloat162float(hi));
                    }
                } else {
                    float4 v = make_float4(vv[0],vv[1],vv[2],vv[3]);
                    *(float4*)&g_Cf[(size_t)lh*HD*HD + (size_t)r*HD + c] = v;
                }
            }
        }
}

// ---------------- buildY: only sec1 = x(n-1)+x(n+1) (1.5x at endpoints) --
__global__ __launch_bounds__(256) void buildY() {
    int node = blockIdx.x * 8 + (threadIdx.x >> 5);
    int lane = threadIdx.x & 31;
    int half = node >= NB ? 1 : 0;
    int i = node - half * NB;
    int c = lane * 8;
    float f[8] = {0.f,0.f,0.f,0.f,0.f,0.f,0.f,0.f};
    if (i > 0) {
        float a[8]; unpack8(*(const uint4*)&g_xh[(size_t)(node-1)*HD + c], a);
        #pragma unroll
        for (int j = 0; j < 8; j++) f[j] += a[j];
    }
    if (i < NB - 1) {
        float a[8]; unpack8(*(const uint4*)&g_xh[(size_t)(node+1)*HD + c], a);
        #pragma unroll
        for (int j = 0; j < 8; j++) f[j] += a[j];
    }
    if (i == 0 || i == NB - 1) {
        #pragma unroll
        for (int j = 0; j < 8; j++) f[j] *= 1.5f;
    }
    *(uint4*)&g_Y[(size_t)node*KTOT + 256 + c] = pack8(f);
}

// ---------------- tensor-core GEMM: u = Y @ W'^T (K=768, contiguous Y) ---
#define MAT_SZ  10240            // 128 rows * 80 B
#define STG_TOT 30720            // AH | BH | BL
#define SMEM_MMA 67584

__global__ __launch_bounds__(256, 2) void gemm_mma(int l) {
    extern __shared__ __align__(16) char sm[];
    uint32_t sb = smem_u32(sm);
    int tid = threadIdx.x, wid = tid >> 5, lane = tid & 31;
    int cb = blockIdx.x, rb = blockIdx.y, half = blockIdx.z;
    int lh = l*2 + half;
    const __nv_bfloat16* Bwh = g_wth + (size_t)lh*HD*KTOT;
    const __nv_bfloat16* Bwl = g_wtl + (size_t)lh*HD*KTOT;

    int lr0 = tid >> 2, lseg = tid & 3;
    int r0 = rb*128 + lr0;      if (r0 >= NB) r0 = NB-1;
    int r1 = rb*128 + lr0 + 64; if (r1 >= NB) r1 = NB-1;
    size_t an0 = (size_t)(half*NB + r0) * KTOT;
    size_t an1 = (size_t)(half*NB + r1) * KTOT;
    size_t bn0 = (size_t)(cb*128 + lr0) * KTOT;
    size_t bn1 = (size_t)(cb*128 + lr0 + 64) * KTOT;

    #define LOAD_STAGE(s, k0) do {                                             \
        uint32_t d0 = sb + (uint32_t)(s)*STG_TOT + lr0*80 + lseg*16;           \
        uint32_t d1 = d0 + 64*80;                                              \
        size_t ka = (size_t)(k0) + lseg*8;                                     \
        cpa16(d0,            g_Y + an0 + ka);                                  \
        cpa16(d1,            g_Y + an1 + ka);                                  \
        cpa16(d0 + MAT_SZ,   Bwh + bn0 + ka);                                  \
        cpa16(d1 + MAT_SZ,   Bwh + bn1 + ka);                                  \
        cpa16(d0 + 2*MAT_SZ, Bwl + bn0 + ka);                                  \
        cpa16(d1 + 2*MAT_SZ, Bwl + bn1 + ka);                                  \
        asm volatile("cp.async.commit_group;" ::: "memory");                   \
    } while (0)

    float acc[4][4][4];
    #pragma unroll
    for (int i = 0; i < 4; i++)
        #pragma unroll
        for (int j = 0; j < 4; j++)
            #pragma unroll
            for (int q = 0; q < 4; q++) acc[i][j][q] = 0.f;

    LOAD_STAGE(0, 0);
    LOAD_STAGE(1, 32);

    int warp_m = (wid >> 2) * 64, warp_n = (wid & 3) * 32;
    int la7 = lane & 7, lb8 = (lane >> 3) & 1, lhi = lane >> 4;
    uint32_t aoff = (uint32_t)(warp_m + la7 + lb8*8)*80 + lhi*16;
    uint32_t boff = MAT_SZ + (uint32_t)(warp_n + lhi*8 + la7)*80 + lb8*16;

    #pragma unroll 1
    for (int kt = 0; kt < 24; kt++) {
        if (kt < 23) asm volatile("cp.async.wait_group 1;" ::: "memory");
        else         asm volatile("cp.async.wait_group 0;" ::: "memory");
        __syncthreads();
        uint32_t stg = sb + (uint32_t)(kt & 1) * STG_TOT;
        #pragma unroll
        for (int k16 = 0; k16 < 2; k16++) {
            uint32_t ko = k16 * 32;
            uint32_t ah[4][4];
            #pragma unroll
            for (int i = 0; i < 4; i++)
                LDM4(ah[i], stg + aoff + i*1280 + ko);
            #pragma unroll
            for (int jj = 0; jj < 2; jj++) {
                uint32_t bh[4], bl[4];
                LDM4(bh, stg + boff + jj*1280 + ko);
                LDM4(bl, stg + MAT_SZ + boff + jj*1280 + ko);
                #pragma unroll
                for (int j2 = 0; j2 < 2; j2++) {
                    int j = jj*2 + j2;
                    #pragma unroll
                    for (int i = 0; i < 4; i++) {
                        MMA2(acc[i][j], ah[i], bh[j2*2], bh[j2*2+1]);
                        MMA2(acc[i][j], ah[i], bl[j2*2], bl[j2*2+1]);
                    }
                }
            }
        }
        __syncthreads();
        if (kt + 2 < 24) LOAD_STAGE(kt & 1, (kt + 2) * 32);
    }

    asm volatile("cp.async.wait_group 0;" ::: "memory");
    __syncthreads();
    float* Cs = (float*)sm;                    // 128 x 132 floats
    int g = lane >> 2;
    int ct = (lane & 3) * 2;
    #pragma unroll
    for (int i = 0; i < 4; i++)
        #pragma unroll
        for (int j = 0; j < 4; j++) {
            int r = warp_m + i*16 + g;
            int c = warp_n + j*8 + ct;
            *(float2*)&Cs[(size_t)r*132 + c]      = make_float2(acc[i][j][0], acc[i][j][1]);
            *(float2*)&Cs[(size_t)(r+8)*132 + c]  = make_float2(acc[i][j][2], acc[i][j][3]);
        }
    __syncthreads();
    #pragma unroll
    for (int it = 0; it < 16; it++) {
        int idx = tid + it*256;
        int r = idx >> 5, c4 = (idx & 31) * 4;
        int node = rb*128 + r;
        if (node < NB) {
            float4 v = *(float4*)&Cs[(size_t)r*132 + c4];
            uint2 pk;
            pk.x = pk2(v.x, v.y); pk.y = pk2(v.z, v.w);
            *(uint2*)&g_U[((size_t)(half*NB + node))*HD + cb*128 + c4] = pk;
        }
    }
    #undef LOAD_STAGE
}

// ---------------- ep_fix: g_U[endpoint] += Cf@x + (bias2 - bias) ---------
__global__ void ep_fix(int l) {
    int e  = blockIdx.x >> 3;
    int cc = blockIdx.x & 7;
    int half = e >> 1;
    int i = (e & 1) ? NB - 1 : 0;
    int node = half * NB + i;
    int lh = l*2 + half;
    int tid = threadIdx.x;
    int col = cc*32 + (tid & 31);
    int kg  = tid >> 5;

    __shared__ float xs[HD];
    __shared__ float red[8][33];
    xs[tid] = __bfloat162float(g_xh[(size_t)node*HD + tid]);
    __syncthreads();

    const float* Cf = g_Cf + (size_t)lh*HD*HD;
    float p = 0.f;
    #pragma unroll 8
    for (int k = kg*32; k < kg*32 + 32; k++)
        p = fmaf(xs[k], Cf[(size_t)k*HD + col], p);
    red[kg][tid & 31] = p;
    __syncthreads();
    if (kg == 0) {
        float s = 0.f;
        #pragma unroll
        for (int w = 0; w < 8; w++) s += red[w][tid & 31];
        size_t o = (size_t)node*HD + col;
        float u = __bfloat162float(g_U[o]) + s
                + g_bias2[lh*HD + col] - g_bias[lh*HD + col];
        g_U[o] = __float2bfloat16(u);
    }
}

// ---------------- combine2: LN + GeLU + residual + Y scatter -------------
__global__ __launch_bounds__(256) void combine2(int l,
        const float* __restrict__ ln_g, const float* __restrict__ ln_b) {
    int node = blockIdx.x * 8 + (threadIdx.x >> 5);
    int lane = threadIdx.x & 31;
    int half = node >= NB ? 1 : 0;
    int i = node - half * NB;
    int p = half ? node - NB : node + NB;
    int c = lane * 8;

    float u[8];
    unpack8(*(const uint4*)&g_U[(size_t)node*HD + c], u);
    const float* bi = g_bias + (l*2 + half) * HD;
    float4 bi0 = ld4(bi + c), bi1 = ld4(bi + c + 4);
    u[0]+=bi0.x; u[1]+=bi0.y; u[2]+=bi0.z; u[3]+=bi0.w;
    u[4]+=bi1.x; u[5]+=bi1.y; u[6]+=bi1.z; u[7]+=bi1.w;

    float s = 0.f, q = 0.f;
    #pragma unroll
    for (int j = 0; j < 8; j++) { s += u[j]; q = fmaf(u[j], u[j], q); }
    #pragma unroll
    for (int off = 16; off; off >>= 1) {
        s += __shfl_xor_sync(0xffffffff, s, off);
        q += __shfl_xor_sync(0xffffffff, q, off);
    }
    float mu = s * (1.f/HD);
    float rs = rsqrtf(q * (1.f/HD) - mu*mu + 1e-5f);

    float4 g0 = ld4(ln_g + l*HD + c), g1 = ld4(ln_g + l*HD + c + 4);
    float4 b0 = ld4(ln_b + l*HD + c), b1 = ld4(ln_b + l*HD + c + 4);
    float gg[8] = {g0.x,g0.y,g0.z,g0.w,g1.x,g1.y,g1.z,g1.w};
    float bb[8] = {b0.x,b0.y,b0.z,b0.w,b1.x,b1.y,b1.z,b1.w};

    float x8[8];
    unpack8(*(const uint4*)&g_xh[(size_t)node*HD + c], x8);
    #pragma unroll
    for (int j = 0; j < 8; j++)
        x8[j] += gelu_exact((u[j] - mu) * rs * gg[j] + bb[j]);
    uint4 pk = pack8(x8);
    *(uint4*)&g_xh[(size_t)node*HD + c] = pk;
    *(uint4*)&g_Y[(size_t)node*KTOT + c] = pk;              // sec0
    uint4 pk2v = pk;
    if (i == 0 || i == NB - 1) {
        float sx[8];
        #pragma unroll
        for (int j = 0; j < 8; j++) sx[j] = x8[j] * 1.5f;
        pk2v = pack8(sx);
    }
    *(uint4*)&g_Y[(size_t)p*KTOT + 512 + c] = pk2v;         // sec2 of partner
}

// ---------------- readout ----------------
__global__ void colmean() {
    int c = threadIdx.x;
    int r0 = blockIdx.x * 100;
    float s = 0.f;
    for (int r = r0; r < r0 + 100; r++)
        s += __bfloat162float(g_xh[(size_t)r * HD + c]);
    g_part[blockIdx.x * HD + c] = s;
}

__global__ void decoder(const float* __restrict__ dec1_w, const float* __restrict__ dec1_b,
                        const float* __restrict__ dec2_w, const float* __restrict__ dec2_b,
                        const float* __restrict__ Kp, const float* __restrict__ tau,
                        const float* __restrict__ tau_max, const float* __restrict__ lam,
                        float* __restrict__ out) {
    __shared__ float hm[HD], z[HD], red[64];
    int t = threadIdx.x;
    float acc0 = 0.f;
    for (int b = 0; b < 200; b++) acc0 += g_part[b * HD + t];
    hm[t] = acc0 * (1.0f / NB);
    __syncthreads();
    float acc = dec1_b[t];
    for (int k = 0; k < HD; k++) acc += hm[k] * dec1_w[k * HD + t];
    z[t] = gelu_exact(acc);
    __syncthreads();
    if (t < 128) {
        float a = dec2_b[t];
        for (int k = 0; k < HD; k++) a += z[k] * dec2_w[k * 128 + t];
        out[t] = a;
    }
    if (t < 64) {
        red[t] = Kp[t] * tau[t] / tau_max[t];
        out[129 + t] = Kp[t];
    }
    __syncthreads();
    if (t == 0) {
        float s = 0.f;
        for (int i = 0; i < 64; i++) s += red[i];
        out[128] = fabsf(lam[0]) - s;
    }
}

// ---------------- launch ----------------
extern "C" void kernel_launch(void* const* d_in, const int* in_sizes, int n_in,
                              void* d_out, int out_size) {
    const float* energy_x     = (const float*)d_in[0];
    const float* comm_x       = (const float*)d_in[1];
    const float* tau          = (const float*)d_in[2];
    const float* tau_max      = (const float*)d_in[3];
    const float* lambda_min_0 = (const float*)d_in[4];
    const float* We_w         = (const float*)d_in[5];
    const float* We_b         = (const float*)d_in[6];
    const float* Wc_w         = (const float*)d_in[7];
    const float* Wc_b         = (const float*)d_in[8];
    const float* msg_w        = (const float*)d_in[9];
    const float* msg_b        = (const float*)d_in[10];
    const float* upd_w        = (const float*)d_in[11];
    const float* upd_b        = (const float*)d_in[12];
    const float* ln_g         = (const float*)d_in[13];
    const float* ln_b         = (const float*)d_in[14];
    const float* dec1_w       = (const float*)d_in[15];
    const float* dec1_b       = (const float*)d_in[16];
    const float* dec2_w       = (const float*)d_in[17];
    const float* dec2_b       = (const float*)d_in[18];
    const float* K_param      = (const float*)d_in[19];
    float* out = (float*)d_out;

    cudaFuncSetAttribute(gemm_mma, cudaFuncAttributeMaxDynamicSharedMemorySize, SMEM_MMA);

    gemm_pre<<<dim3(9, 2, 8), 256>>>(msg_w, upd_w, msg_b, upd_b);
    encode<<<(TWO_N * HD / 8 + 255) / 256, 256>>>(energy_x, comm_x, We_w, We_b, Wc_w, Wc_b);

    for (int l = 0; l < NL; l++) {
        buildY<<<TWO_N / 8, 256>>>();
        gemm_mma<<<dim3(2, (NB + 127) / 128, 2), 256, SMEM_MMA>>>(l);
        ep_fix<<<32, 256>>>(l);
        combine2<<<TWO_N / 8, 256>>>(l, ln_g, ln_b);
    }

    colmean<<<200, 256>>>();
    decoder<<<1, 256>>>(dec1_w, dec1_b, dec2_w, dec2_b,
                        K_param, tau, tau_max, lambda_min_0, out);
}

// round 16
// speedup vs baseline: 1.0800x; 1.0006x over previous
#include <cuda_runtime.h>
#include <cuda_bf16.h>
#include <math.h>
#include <stdint.h>

#define NB 20000
#define HD 256
#define NL 4
#define TWO_N (2*NB)
#define KTOT 768
#define MT 96                    // M tile

// ---------------- device scratch ----------------
__device__ __nv_bfloat16 g_xh[(size_t)TWO_N * HD];          // h (bf16, sole copy)
__device__ __nv_bfloat16 g_Y [(size_t)TWO_N * KTOT];        // [x | nbr-sum | x(p)]
__device__ __nv_bfloat16 g_U [(size_t)TWO_N * HD];          // u (pre-LN), bf16
__device__ __nv_bfloat16 g_wth[(size_t)NL * 2 * HD * KTOT]; // W' hi [lh][n256][k768]
__device__ __nv_bfloat16 g_wtl[(size_t)NL * 2 * HD * KTOT]; // W' lo
__device__ float g_Cf [(size_t)NL * 2 * HD * HD];           // endpoint fixup (B2-Bh)U2/6
__device__ float g_bias [NL * 2 * HD];
__device__ float g_bias2[NL * 2 * HD];
__device__ float g_part[200 * HD];

// ---------------- helpers ----------------
__device__ __forceinline__ float gelu_exact(float x) {
    return 0.5f * x * (1.0f + erff(x * 0.70710678118654752f));
}
__device__ __forceinline__ float4 ld4(const float* p) { return *(const float4*)p; }
__device__ __forceinline__ float4 f4fma(float s, float4 a, float4 b) {
    return make_float4(fmaf(s,a.x,b.x), fmaf(s,a.y,b.y), fmaf(s,a.z,b.z), fmaf(s,a.w,b.w));
}
__device__ __forceinline__ float bflo(uint32_t u) { return __uint_as_float(u << 16); }
__device__ __forceinline__ float bfhi(uint32_t u) { return __uint_as_float(u & 0xffff0000u); }
__device__ __forceinline__ void unpack8(uint4 u, float* f) {
    f[0]=bflo(u.x); f[1]=bfhi(u.x); f[2]=bflo(u.y); f[3]=bfhi(u.y);
    f[4]=bflo(u.z); f[5]=bfhi(u.z); f[6]=bflo(u.w); f[7]=bfhi(u.w);
}
__device__ __forceinline__ uint32_t pk2(float a, float b) {
    __nv_bfloat162 t(__float2bfloat16(a), __float2bfloat16(b));
    return *(uint32_t*)&t;
}
__device__ __forceinline__ uint4 pack8(const float* f) {
    uint4 u;
    u.x = pk2(f[0],f[1]); u.y = pk2(f[2],f[3]);
    u.z = pk2(f[4],f[5]); u.w = pk2(f[6],f[7]);
    return u;
}
__device__ __forceinline__ uint32_t smem_u32(const void* p) {
    uint32_t a;
    asm("{ .reg .u64 t; cvta.to.shared.u64 t, %1; cvt.u32.u64 %0, t; }" : "=r"(a) : "l"(p));
    return a;
}
__device__ __forceinline__ void cpa16(uint32_t s, const void* g) {
    asm volatile("cp.async.cg.shared.global [%0], [%1], 16;" :: "r"(s), "l"(g));
}

#define MMA2(c, A, b0v, b1v) asm volatile( \
    "mma.sync.aligned.m16n8k16.row.col.f32.bf16.bf16.f32 " \
    "{%0,%1,%2,%3},{%4,%5,%6,%7},{%8,%9},{%0,%1,%2,%3};" \
    : "+f"(c[0]),"+f"(c[1]),"+f"(c[2]),"+f"(c[3]) \
    : "r"(A[0]),"r"(A[1]),"r"(A[2]),"r"(A[3]),"r"(b0v),"r"(b1v))

#define LDM4(r, addr) asm volatile( \
    "ldmatrix.sync.aligned.m8n8.x4.shared.b16 {%0,%1,%2,%3}, [%4];" \
    : "=r"((r)[0]),"=r"((r)[1]),"=r"((r)[2]),"=r"((r)[3]) : "r"(addr))

// ---------------- encode: x -> g_xh, g_Y sec0, g_Y[partner] sec2 ---------
__global__ void encode(const float* __restrict__ ex, const float* __restrict__ cx,
                       const float* __restrict__ Wew, const float* __restrict__ Web,
                       const float* __restrict__ Wcw, const float* __restrict__ Wcb) {
    int idx = blockIdx.x * blockDim.x + threadIdx.x;
    if (idx >= TWO_N * HD / 8) return;
    int c = (idx & 31) * 8;
    int g = idx >> 5;
    float f[8];
    if (g < NB) {
        const float* x = ex + (size_t)g * 5;
        float4 v0 = ld4(&Web[c]), v1 = ld4(&Web[c+4]);
        #pragma unroll
        for (int j = 0; j < 5; j++) {
            v0 = f4fma(x[j], ld4(&Wew[j * HD + c]),   v0);
            v1 = f4fma(x[j], ld4(&Wew[j * HD + c+4]), v1);
        }
        f[0]=v0.x; f[1]=v0.y; f[2]=v0.z; f[3]=v0.w; f[4]=v1.x; f[5]=v1.y; f[6]=v1.z; f[7]=v1.w;
    } else {
        const float* x = cx + (size_t)(g - NB) * 3;
        float4 v0 = ld4(&Wcb[c]), v1 = ld4(&Wcb[c+4]);
        #pragma unroll
        for (int j = 0; j < 3; j++) {
            v0 = f4fma(x[j], ld4(&Wcw[j * HD + c]),   v0);
            v1 = f4fma(x[j], ld4(&Wcw[j * HD + c+4]), v1);
        }
        f[0]=v0.x; f[1]=v0.y; f[2]=v0.z; f[3]=v0.w; f[4]=v1.x; f[5]=v1.y; f[6]=v1.z; f[7]=v1.w;
    }
    uint4 pk = pack8(f);
    *(uint4*)&g_xh[(size_t)g * HD + c] = pk;
    *(uint4*)&g_Y[(size_t)g * KTOT + c] = pk;                 // sec0
    int half = g >= NB ? 1 : 0;
    int i = g - half * NB;
    int p = half ? g - NB : g + NB;
    uint4 pk2v = pk;
    if (i == 0 || i == NB - 1) {
        float s[8];
        #pragma unroll
        for (int j = 0; j < 8; j++) s[j] = f[j] * 1.5f;
        pk2v = pack8(s);
    }
    *(uint4*)&g_Y[(size_t)p * KTOT + 512 + c] = pk2v;         // sec2 of partner
}

// ---------------- weight folding ----------------
// sec0: S=U1+(2Bh+B2)U2/3 ; sec1: A_h U2/3 ; sec2: A2 U2/3 (-> W' bf16)
// sec3: Cf=(B2-Bh)U2/6 (fp32). cb==8: bias folding.
__global__ __launch_bounds__(256, 2) void gemm_pre(const float* __restrict__ msg_w,
                                                   const float* __restrict__ upd_w,
                                                   const float* __restrict__ msg_b,
                                                   const float* __restrict__ upd_b) {
    int cb = blockIdx.x, rb = blockIdx.y, lh = blockIdx.z;
    int l = lh >> 1, h = lh & 1;

    __shared__ float As[2][16][132];
    __shared__ float Bs[2][16][128];
    int tid = threadIdx.x;

    if (cb == 8) {
        if (rb != 0) return;
        float* v1 = &As[0][0][0];
        float* v2 = v1 + HD;
        int c = tid;
        float mbh = msg_b[(l*3 + h)*HD + c];
        float mb2 = msg_b[(l*3 + 2)*HD + c];
        v1[c] = 2.f*mbh + mb2;
        v2[c] = mbh + mb2;
        __syncthreads();
        const float* U2 = upd_w + ((size_t)l*512 + HD) * HD;
        float s1 = 0.f, s2 = 0.f;
        for (int k = 0; k < HD; k++) {
            float u = U2[(size_t)k*HD + c];
            s1 += v1[k]*u; s2 += v2[k]*u;
        }
        g_bias [lh*HD + c] = s1*(1.f/3.f) + upd_b[l*HD + c];
        g_bias2[lh*HD + c] = s2*0.5f     + upd_b[l*HD + c];
        return;
    }

    int sec = cb >> 1;
    int col0 = (cb & 1) * 128;
    int row0 = rb * 128;
    const float* mh = msg_w + (size_t)(l*3 + h) * 512 * HD;
    const float* m2 = msg_w + (size_t)(l*3 + 2) * 512 * HD;
    const float* U1 = upd_w + (size_t)l * 512 * HD;
    const float* U2 = U1 + (size_t)HD * HD;
    const float* P1; const float* P2; float w1, w2, scale; int addU1;
    if (sec == 0)      { P1 = mh + HD*HD; w1 = 2.f; P2 = m2 + HD*HD; w2 = 1.f;  scale = 1.f/3.f; addU1 = 1; }
    else if (sec == 1) { P1 = mh;          w1 = 1.f; P2 = 0;          w2 = 0.f;  scale = 1.f/3.f; addU1 = 0; }
    else if (sec == 2) { P1 = m2;          w1 = 1.f; P2 = 0;          w2 = 0.f;  scale = 1.f/3.f; addU1 = 0; }
    else               { P1 = m2 + HD*HD; w1 = 1.f; P2 = mh + HD*HD; w2 = -1.f; scale = 1.f/6.f; addU1 = 0; }

    int tx = tid & 15, ty = tid >> 4;
    int ar = tid >> 2, ak = (tid & 3) * 4;
    int bk = tid >> 5, bn = (tid & 31) * 4;

    float acc[8][8];
    #pragma unroll
    for (int i = 0; i < 8; i++)
        #pragma unroll
        for (int j = 0; j < 8; j++) acc[i][j] = 0.f;

    float4 a0v, a1v, b0v, b1v;
    {
        int r0 = row0 + ar, r1 = row0 + ar + 64;
        a0v = ld4(&P1[(size_t)r0*HD + ak]);
        a1v = ld4(&P1[(size_t)r1*HD + ak]);
        if (P2) { a0v = f4fma(w2/w1, ld4(&P2[(size_t)r0*HD + ak]), a0v);
                  a1v = f4fma(w2/w1, ld4(&P2[(size_t)r1*HD + ak]), a1v); }
        b0v = ld4(&U2[(size_t)bk*HD + col0 + bn]);
        b1v = ld4(&U2[(size_t)(bk+8)*HD + col0 + bn]);
    }
    As[0][ak+0][ar]=a0v.x; As[0][ak+1][ar]=a0v.y; As[0][ak+2][ar]=a0v.z; As[0][ak+3][ar]=a0v.w;
    As[0][ak+0][64+ar]=a1v.x; As[0][ak+1][64+ar]=a1v.y; As[0][ak+2][64+ar]=a1v.z; As[0][ak+3][64+ar]=a1v.w;
    *(float4*)&Bs[0][bk][bn] = b0v; *(float4*)&Bs[0][bk+8][bn] = b1v;
    __syncthreads();

    int buf = 0;
    #pragma unroll 1
    for (int t = 0; t < 16; t++) {
        if (t < 15) {
            int k0 = (t + 1) * 16;
            int r0 = row0 + ar, r1 = row0 + ar + 64;
            a0v = ld4(&P1[(size_t)r0*HD + k0 + ak]);
            a1v = ld4(&P1[(size_t)r1*HD + k0 + ak]);
            if (P2) { a0v = f4fma(w2/w1, ld4(&P2[(size_t)r0*HD + k0 + ak]), a0v);
                      a1v = f4fma(w2/w1, ld4(&P2[(size_t)r1*HD + k0 + ak]), a1v); }
            b0v = ld4(&U2[(size_t)(k0+bk)*HD + col0 + bn]);
            b1v = ld4(&U2[(size_t)(k0+bk+8)*HD + col0 + bn]);
        }
        #pragma unroll
        for (int k = 0; k < 16; k++) {
            float4 pa0 = *(float4*)&As[buf][k][ty*4];
            float4 pa1 = *(float4*)&As[buf][k][64 + ty*4];
            float4 pb0 = *(float4*)&Bs[buf][k][tx*4];
            float4 pb1 = *(float4*)&Bs[buf][k][64 + tx*4];
            float aa[8] = {pa0.x,pa0.y,pa0.z,pa0.w,pa1.x,pa1.y,pa1.z,pa1.w};
            float bb[8] = {pb0.x,pb0.y,pb0.z,pb0.w,pb1.x,pb1.y,pb1.z,pb1.w};
            #pragma unroll
            for (int i = 0; i < 8; i++)
                #pragma unroll
                for (int j = 0; j < 8; j++)
                    acc[i][j] = fmaf(aa[i], bb[j], acc[i][j]);
        }
        if (t < 15) {
            int nb2 = buf ^ 1;
            As[nb2][ak+0][ar]=a0v.x; As[nb2][ak+1][ar]=a0v.y; As[nb2][ak+2][ar]=a0v.z; As[nb2][ak+3][ar]=a0v.w;
            As[nb2][ak+0][64+ar]=a1v.x; As[nb2][ak+1][64+ar]=a1v.y; As[nb2][ak+2][64+ar]=a1v.z; As[nb2][ak+3][64+ar]=a1v.w;
            *(float4*)&Bs[nb2][bk][bn] = b0v; *(float4*)&Bs[nb2][bk+8][bn] = b1v;
        }
        __syncthreads();
        buf ^= 1;
    }

    float sc = w1 * scale;
    #pragma unroll
    for (int ih = 0; ih < 2; ih++)
        #pragma unroll
        for (int ii = 0; ii < 4; ii++) {
            int r = row0 + ih*64 + ty*4 + ii;          // k index (0..255)
            #pragma unroll
            for (int jh = 0; jh < 2; jh++) {
                int c = col0 + jh*64 + tx*4;           // n index (0..255)
                float vv[4];
                #pragma unroll
                for (int j = 0; j < 4; j++) vv[j] = acc[ih*4+ii][jh*4+j] * sc;
                if (addU1) {
                    float4 u = ld4(&U1[(size_t)r*HD + c]);
                    vv[0]+=u.x; vv[1]+=u.y; vv[2]+=u.z; vv[3]+=u.w;
                }
                if (sec < 3) {
                    #pragma unroll
                    for (int j = 0; j < 4; j++) {
                        size_t o = ((size_t)lh*HD + (c + j))*KTOT + sec*HD + r;
                        __nv_bfloat16 hi = __float2bfloat16(vv[j]);
                        g_wth[o] = hi;
                        g_wtl[o] = __float2bfloat16(vv[j] - __bfloat162float(hi));
                    }
                } else {
                    float4 v = make_float4(vv[0],vv[1],vv[2],vv[3]);
                    *(float4*)&g_Cf[(size_t)lh*HD*HD + (size_t)r*HD + c] = v;
                }
            }
        }
}

// ---------------- buildY: only sec1 = x(n-1)+x(n+1) (1.5x at endpoints) --
__global__ __launch_bounds__(256) void buildY() {
    int node = blockIdx.x * 8 + (threadIdx.x >> 5);
    int lane = threadIdx.x & 31;
    int half = node >= NB ? 1 : 0;
    int i = node - half * NB;
    int c = lane * 8;
    float f[8] = {0.f,0.f,0.f,0.f,0.f,0.f,0.f,0.f};
    if (i > 0) {
        float a[8]; unpack8(*(const uint4*)&g_xh[(size_t)(node-1)*HD + c], a);
        #pragma unroll
        for (int j = 0; j < 8; j++) f[j] += a[j];
    }
    if (i < NB - 1) {
        float a[8]; unpack8(*(const uint4*)&g_xh[(size_t)(node+1)*HD + c], a);
        #pragma unroll
        for (int j = 0; j < 8; j++) f[j] += a[j];
    }
    if (i == 0 || i == NB - 1) {
        #pragma unroll
        for (int j = 0; j < 8; j++) f[j] *= 1.5f;
    }
    *(uint4*)&g_Y[(size_t)node*KTOT + 256 + c] = pack8(f);
}

// ---------------- tensor-core GEMM: u = Y @ W'^T (K=768, M-tile 96) ------
#define A_SZ    7680             // 96 rows * 80 B
#define B_SZ    10240            // 128 rows * 80 B
#define STG_TOT 28160            // A | BH | BL
#define SMEM_MMA 56320           // 2 stages (C stage 96*132*4=50688 fits)

__global__ __launch_bounds__(256, 2) void gemm_mma(int l) {
    extern __shared__ __align__(16) char sm[];
    uint32_t sb = smem_u32(sm);
    int tid = threadIdx.x, wid = tid >> 5, lane = tid & 31;
    int cb = blockIdx.x, rb = blockIdx.y, half = blockIdx.z;
    int lh = l*2 + half;
    const __nv_bfloat16* Bwh = g_wth + (size_t)lh*HD*KTOT;
    const __nv_bfloat16* Bwl = g_wtl + (size_t)lh*HD*KTOT;

    int lr0 = tid >> 2, lseg = tid & 3;
    int r0 = rb*MT + lr0;      if (r0 >= NB) r0 = NB-1;      // A rows 0..63
    int r1 = rb*MT + 64 + lr0; if (r1 >= NB) r1 = NB-1;      // A rows 64..95 (lr0<32)
    bool doA1 = (lr0 < 32);
    size_t an0 = (size_t)(half*NB + r0) * KTOT;
    size_t an1 = (size_t)(half*NB + r1) * KTOT;
    size_t bn0 = (size_t)(cb*128 + lr0) * KTOT;
    size_t bn1 = (size_t)(cb*128 + lr0 + 64) * KTOT;

    #define LOAD_STAGE(s, k0) do {                                             \
        uint32_t d0 = sb + (uint32_t)(s)*STG_TOT + lr0*80 + lseg*16;           \
        size_t ka = (size_t)(k0) + lseg*8;                                     \
        cpa16(d0, g_Y + an0 + ka);                                             \
        if (doA1) cpa16(d0 + 64*80, g_Y + an1 + ka);                           \
        cpa16(d0 + A_SZ,        Bwh + bn0 + ka);                               \
        cpa16(d0 + A_SZ + 64*80, Bwh + bn1 + ka);                              \
        cpa16(d0 + A_SZ + B_SZ,        Bwl + bn0 + ka);                        \
        cpa16(d0 + A_SZ + B_SZ + 64*80, Bwl + bn1 + ka);                       \
        asm volatile("cp.async.commit_group;" ::: "memory");                   \
    } while (0)

    float acc[3][4][4];
    #pragma unroll
    for (int i = 0; i < 3; i++)
        #pragma unroll
        for (int j = 0; j < 4; j++)
            #pragma unroll
            for (int q = 0; q < 4; q++) acc[i][j][q] = 0.f;

    LOAD_STAGE(0, 0);
    LOAD_STAGE(1, 32);

    int warp_m = (wid >> 2) * 48, warp_n = (wid & 3) * 32;
    int la7 = lane & 7, lb8 = (lane >> 3) & 1, lhi = lane >> 4;
    uint32_t aoff = (uint32_t)(warp_m + la7 + lb8*8)*80 + lhi*16;
    uint32_t boff = A_SZ + (uint32_t)(warp_n + lhi*8 + la7)*80 + lb8*16;

    #pragma unroll 1
    for (int kt = 0; kt < 24; kt++) {
        if (kt < 23) asm volatile("cp.async.wait_group 1;" ::: "memory");
        else         asm volatile("cp.async.wait_group 0;" ::: "memory");
        __syncthreads();
        uint32_t stg = sb + (uint32_t)(kt & 1) * STG_TOT;
        #pragma unroll
        for (int k16 = 0; k16 < 2; k16++) {
            uint32_t ko = k16 * 32;
            uint32_t ah[3][4];
            #pragma unroll
            for (int i = 0; i < 3; i++)
                LDM4(ah[i], stg + aoff + i*1280 + ko);
            #pragma unroll
            for (int jj = 0; jj < 2; jj++) {
                uint32_t bh[4], bl[4];
                LDM4(bh, stg + boff + jj*1280 + ko);
                LDM4(bl, stg + B_SZ + boff + jj*1280 + ko);
                #pragma unroll
                for (int j2 = 0; j2 < 2; j2++) {
                    int j = jj*2 + j2;
                    #pragma unroll
                    for (int i = 0; i < 3; i++) {
                        MMA2(acc[i][j], ah[i], bh[j2*2], bh[j2*2+1]);
                        MMA2(acc[i][j], ah[i], bl[j2*2], bl[j2*2+1]);
                    }
                }
            }
        }
        __syncthreads();
        if (kt + 2 < 24) LOAD_STAGE(kt & 1, (kt + 2) * 32);
    }

    asm volatile("cp.async.wait_group 0;" ::: "memory");
    __syncthreads();
    float* Cs = (float*)sm;                    // 96 x 132 floats
    int g = lane >> 2;
    int ct = (lane & 3) * 2;
    #pragma unroll
    for (int i = 0; i < 3; i++)
        #pragma unroll
        for (int j = 0; j < 4; j++) {
            int r = warp_m + i*16 + g;
            int c = warp_n + j*8 + ct;
            *(float2*)&Cs[(size_t)r*132 + c]      = make_float2(acc[i][j][0], acc[i][j][1]);
            *(float2*)&Cs[(size_t)(r+8)*132 + c]  = make_float2(acc[i][j][2], acc[i][j][3]);
        }
    __syncthreads();
    #pragma unroll
    for (int it = 0; it < 12; it++) {
        int idx = tid + it*256;                // 3072 = 96 rows x 32 float4
        int r = idx >> 5, c4 = (idx & 31) * 4;
        int node = rb*MT + r;
        if (node < NB) {
            float4 v = *(float4*)&Cs[(size_t)r*132 + c4];
            uint2 pk;
            pk.x = pk2(v.x, v.y); pk.y = pk2(v.z, v.w);
            *(uint2*)&g_U[((size_t)(half*NB + node))*HD + cb*128 + c4] = pk;
        }
    }
    #undef LOAD_STAGE
}

// ---------------- ep_fix: g_U[endpoint] += Cf@x + (bias2 - bias) ---------
__global__ void ep_fix(int l) {
    int e  = blockIdx.x >> 3;
    int cc = blockIdx.x & 7;
    int half = e >> 1;
    int i = (e & 1) ? NB - 1 : 0;
    int node = half * NB + i;
    int lh = l*2 + half;
    int tid = threadIdx.x;
    int col = cc*32 + (tid & 31);
    int kg  = tid >> 5;

    __shared__ float xs[HD];
    __shared__ float red[8][33];
    xs[tid] = __bfloat162float(g_xh[(size_t)node*HD + tid]);
    __syncthreads();

    const float* Cf = g_Cf + (size_t)lh*HD*HD;
    float p = 0.f;
    #pragma unroll 8
    for (int k = kg*32; k < kg*32 + 32; k++)
        p = fmaf(xs[k], Cf[(size_t)k*HD + col], p);
    red[kg][tid & 31] = p;
    __syncthreads();
    if (kg == 0) {
        float s = 0.f;
        #pragma unroll
        for (int w = 0; w < 8; w++) s += red[w][tid & 31];
        size_t o = (size_t)node*HD + col;
        float u = __bfloat162float(g_U[o]) + s
                + g_bias2[lh*HD + col] - g_bias[lh*HD + col];
        g_U[o] = __float2bfloat16(u);
    }
}

// ---------------- combine2: LN + GeLU + residual + Y scatter -------------
__global__ __launch_bounds__(256) void combine2(int l,
        const float* __restrict__ ln_g, const float* __restrict__ ln_b) {
    int node = blockIdx.x * 8 + (threadIdx.x >> 5);
    int lane = threadIdx.x & 31;
    int half = node >= NB ? 1 : 0;
    int i = node - half * NB;
    int p = half ? node - NB : node + NB;
    int c = lane * 8;

    float u[8];
    unpack8(*(const uint4*)&g_U[(size_t)node*HD + c], u);
    const float* bi = g_bias + (l*2 + half) * HD;
    float4 bi0 = ld4(bi + c), bi1 = ld4(bi + c + 4);
    u[0]+=bi0.x; u[1]+=bi0.y; u[2]+=bi0.z; u[3]+=bi0.w;
    u[4]+=bi1.x; u[5]+=bi1.y; u[6]+=bi1.z; u[7]+=bi1.w;

    float s = 0.f, q = 0.f;
    #pragma unroll
    for (int j = 0; j < 8; j++) { s += u[j]; q = fmaf(u[j], u[j], q); }
    #pragma unroll
    for (int off = 16; off; off >>= 1) {
        s += __shfl_xor_sync(0xffffffff, s, off);
        q += __shfl_xor_sync(0xffffffff, q, off);
    }
    float mu = s * (1.f/HD);
    float rs = rsqrtf(q * (1.f/HD) - mu*mu + 1e-5f);

    float4 g0 = ld4(ln_g + l*HD + c), g1 = ld4(ln_g + l*HD + c + 4);
    float4 b0 = ld4(ln_b + l*HD + c), b1 = ld4(ln_b + l*HD + c + 4);
    float gg[8] = {g0.x,g0.y,g0.z,g0.w,g1.x,g1.y,g1.z,g1.w};
    float bb[8] = {b0.x,b0.y,b0.z,b0.w,b1.x,b1.y,b1.z,b1.w};

    float x8[8];
    unpack8(*(const uint4*)&g_xh[(size_t)node*HD + c], x8);
    #pragma unroll
    for (int j = 0; j < 8; j++)
        x8[j] += gelu_exact((u[j] - mu) * rs * gg[j] + bb[j]);
    uint4 pk = pack8(x8);
    *(uint4*)&g_xh[(size_t)node*HD + c] = pk;
    *(uint4*)&g_Y[(size_t)node*KTOT + c] = pk;              // sec0
    uint4 pk2v = pk;
    if (i == 0 || i == NB - 1) {
        float sx[8];
        #pragma unroll
        for (int j = 0; j < 8; j++) sx[j] = x8[j] * 1.5f;
        pk2v = pack8(sx);
    }
    *(uint4*)&g_Y[(size_t)p*KTOT + 512 + c] = pk2v;         // sec2 of partner
}

// ---------------- readout ----------------
__global__ void colmean() {
    int c = threadIdx.x;
    int r0 = blockIdx.x * 100;
    float s = 0.f;
    for (int r = r0; r < r0 + 100; r++)
        s += __bfloat162float(g_xh[(size_t)r * HD + c]);
    g_part[blockIdx.x * HD + c] = s;
}

__global__ void decoder(const float* __restrict__ dec1_w, const float* __restrict__ dec1_b,
                        const float* __restrict__ dec2_w, const float* __restrict__ dec2_b,
                        const float* __restrict__ Kp, const float* __restrict__ tau,
                        const float* __restrict__ tau_max, const float* __restrict__ lam,
                        float* __restrict__ out) {
    __shared__ float hm[HD], z[HD], red[64];
    int t = threadIdx.x;
    float acc0 = 0.f;
    for (int b = 0; b < 200; b++) acc0 += g_part[b * HD + t];
    hm[t] = acc0 * (1.0f / NB);
    __syncthreads();
    float acc = dec1_b[t];
    for (int k = 0; k < HD; k++) acc += hm[k] * dec1_w[k * HD + t];
    z[t] = gelu_exact(acc);
    __syncthreads();
    if (t < 128) {
        float a = dec2_b[t];
        for (int k = 0; k < HD; k++) a += z[k] * dec2_w[k * 128 + t];
        out[t] = a;
    }
    if (t < 64) {
        red[t] = Kp[t] * tau[t] / tau_max[t];
        out[129 + t] = Kp[t];
    }
    __syncthreads();
    if (t == 0) {
        float s = 0.f;
        for (int i = 0; i < 64; i++) s += red[i];
        out[128] = fabsf(lam[0]) - s;
    }
}

// ---------------- launch ----------------
extern "C" void kernel_launch(void* const* d_in, const int* in_sizes, int n_in,
                              void* d_out, int out_size) {
    const float* energy_x     = (const float*)d_in[0];
    const float* comm_x       = (const float*)d_in[1];
    const float* tau          = (const float*)d_in[2];
    const float* tau_max      = (const float*)d_in[3];
    const float* lambda_min_0 = (const float*)d_in[4];
    const float* We_w         = (const float*)d_in[5];
    const float* We_b         = (const float*)d_in[6];
    const float* Wc_w         = (const float*)d_in[7];
    const float* Wc_b         = (const float*)d_in[8];
    const float* msg_w        = (const float*)d_in[9];
    const float* msg_b        = (const float*)d_in[10];
    const float* upd_w        = (const float*)d_in[11];
    const float* upd_b        = (const float*)d_in[12];
    const float* ln_g         = (const float*)d_in[13];
    const float* ln_b         = (const float*)d_in[14];
    const float* dec1_w       = (const float*)d_in[15];
    const float* dec1_b       = (const float*)d_in[16];
    const float* dec2_w       = (const float*)d_in[17];
    const float* dec2_b       = (const float*)d_in[18];
    const float* K_param      = (const float*)d_in[19];
    float* out = (float*)d_out;

    cudaFuncSetAttribute(gemm_mma, cudaFuncAttributeMaxDynamicSharedMemorySize, SMEM_MMA);

    gemm_pre<<<dim3(9, 2, 8), 256>>>(msg_w, upd_w, msg_b, upd_b);
    encode<<<(TWO_N * HD / 8 + 255) / 256, 256>>>(energy_x, comm_x, We_w, We_b, Wc_w, Wc_b);

    for (int l = 0; l < NL; l++) {
        buildY<<<TWO_N / 8, 256>>>();
        gemm_mma<<<dim3(2, (NB + MT - 1) / MT, 2), 256, SMEM_MMA>>>(l);
        ep_fix<<<32, 256>>>(l);
        combine2<<<TWO_N / 8, 256>>>(l, ln_g, ln_b);
    }

    colmean<<<200, 256>>>();
    decoder<<<1, 256>>>(dec1_w, dec1_b, dec2_w, dec2_b,
                        K_param, tau, tau_max, lambda_min_0, out);
}

// round 17
// speedup vs baseline: 1.1189x; 1.0360x over previous
#include <cuda_runtime.h>
#include <cuda_bf16.h>
#include <math.h>
#include <stdint.h>

#define NB 20000
#define HD 256
#define NL 4
#define TWO_N (2*NB)
#define KTOT 768

// ---------------- device scratch ----------------
__device__ __nv_bfloat16 g_xh[(size_t)TWO_N * HD];          // h (bf16, sole copy)
__device__ __nv_bfloat16 g_Y [(size_t)TWO_N * KTOT];        // [x | nbr-sum | x(p)]
__device__ __nv_bfloat16 g_U [(size_t)TWO_N * HD];          // u (pre-LN), bf16
__device__ __nv_bfloat16 g_wth[(size_t)NL * 2 * HD * KTOT]; // W' hi [lh][n256][k768]
__device__ __nv_bfloat16 g_wtl[(size_t)NL * 2 * HD * KTOT]; // W' lo
__device__ float g_Cf [(size_t)NL * 2 * HD * HD];           // endpoint fixup (B2-Bh)U2/6
__device__ float g_bias [NL * 2 * HD];
__device__ float g_bias2[NL * 2 * HD];
__device__ float g_part[200 * HD];

// ---------------- helpers ----------------
__device__ __forceinline__ float gelu_exact(float x) {
    return 0.5f * x * (1.0f + erff(x * 0.70710678118654752f));
}
__device__ __forceinline__ float4 ld4(const float* p) { return *(const float4*)p; }
__device__ __forceinline__ float4 f4fma(float s, float4 a, float4 b) {
    return make_float4(fmaf(s,a.x,b.x), fmaf(s,a.y,b.y), fmaf(s,a.z,b.z), fmaf(s,a.w,b.w));
}
__device__ __forceinline__ float bflo(uint32_t u) { return __uint_as_float(u << 16); }
__device__ __forceinline__ float bfhi(uint32_t u) { return __uint_as_float(u & 0xffff0000u); }
__device__ __forceinline__ void unpack8(uint4 u, float* f) {
    f[0]=bflo(u.x); f[1]=bfhi(u.x); f[2]=bflo(u.y); f[3]=bfhi(u.y);
    f[4]=bflo(u.z); f[5]=bfhi(u.z); f[6]=bflo(u.w); f[7]=bfhi(u.w);
}
__device__ __forceinline__ uint32_t pk2(float a, float b) {
    __nv_bfloat162 t(__float2bfloat16(a), __float2bfloat16(b));
    return *(uint32_t*)&t;
}
__device__ __forceinline__ uint4 pack8(const float* f) {
    uint4 u;
    u.x = pk2(f[0],f[1]); u.y = pk2(f[2],f[3]);
    u.z = pk2(f[4],f[5]); u.w = pk2(f[6],f[7]);
    return u;
}
__device__ __forceinline__ uint32_t smem_u32(const void* p) {
    uint32_t a;
    asm("{ .reg .u64 t; cvta.to.shared.u64 t, %1; cvt.u32.u64 %0, t; }" : "=r"(a) : "l"(p));
    return a;
}
__device__ __forceinline__ void cpa16(uint32_t s, const void* g) {
    asm volatile("cp.async.cg.shared.global [%0], [%1], 16;" :: "r"(s), "l"(g));
}

#define MMA2(c, A, b0v, b1v) asm volatile( \
    "mma.sync.aligned.m16n8k16.row.col.f32.bf16.bf16.f32 " \
    "{%0,%1,%2,%3},{%4,%5,%6,%7},{%8,%9},{%0,%1,%2,%3};" \
    : "+f"(c[0]),"+f"(c[1]),"+f"(c[2]),"+f"(c[3]) \
    : "r"(A[0]),"r"(A[1]),"r"(A[2]),"r"(A[3]),"r"(b0v),"r"(b1v))

#define LDM4(r, addr) asm volatile( \
    "ldmatrix.sync.aligned.m8n8.x4.shared.b16 {%0,%1,%2,%3}, [%4];" \
    : "=r"((r)[0]),"=r"((r)[1]),"=r"((r)[2]),"=r"((r)[3]) : "r"(addr))

// ---------------- encode: x -> g_xh, g_Y sec0, g_Y[partner] sec2 ---------
__global__ void encode(const float* __restrict__ ex, const float* __restrict__ cx,
                       const float* __restrict__ Wew, const float* __restrict__ Web,
                       const float* __restrict__ Wcw, const float* __restrict__ Wcb) {
    int idx = blockIdx.x * blockDim.x + threadIdx.x;
    if (idx >= TWO_N * HD / 8) return;
    int c = (idx & 31) * 8;
    int g = idx >> 5;
    float f[8];
    if (g < NB) {
        const float* x = ex + (size_t)g * 5;
        float4 v0 = ld4(&Web[c]), v1 = ld4(&Web[c+4]);
        #pragma unroll
        for (int j = 0; j < 5; j++) {
            v0 = f4fma(x[j], ld4(&Wew[j * HD + c]),   v0);
            v1 = f4fma(x[j], ld4(&Wew[j * HD + c+4]), v1);
        }
        f[0]=v0.x; f[1]=v0.y; f[2]=v0.z; f[3]=v0.w; f[4]=v1.x; f[5]=v1.y; f[6]=v1.z; f[7]=v1.w;
    } else {
        const float* x = cx + (size_t)(g - NB) * 3;
        float4 v0 = ld4(&Wcb[c]), v1 = ld4(&Wcb[c+4]);
        #pragma unroll
        for (int j = 0; j < 3; j++) {
            v0 = f4fma(x[j], ld4(&Wcw[j * HD + c]),   v0);
            v1 = f4fma(x[j], ld4(&Wcw[j * HD + c+4]), v1);
        }
        f[0]=v0.x; f[1]=v0.y; f[2]=v0.z; f[3]=v0.w; f[4]=v1.x; f[5]=v1.y; f[6]=v1.z; f[7]=v1.w;
    }
    uint4 pk = pack8(f);
    *(uint4*)&g_xh[(size_t)g * HD + c] = pk;
    *(uint4*)&g_Y[(size_t)g * KTOT + c] = pk;                 // sec0
    int half = g >= NB ? 1 : 0;
    int i = g - half * NB;
    int p = half ? g - NB : g + NB;
    uint4 pk2v = pk;
    if (i == 0 || i == NB - 1) {
        float s[8];
        #pragma unroll
        for (int j = 0; j < 8; j++) s[j] = f[j] * 1.5f;
        pk2v = pack8(s);
    }
    *(uint4*)&g_Y[(size_t)p * KTOT + 512 + c] = pk2v;         // sec2 of partner
}

// ---------------- weight folding ----------------
// sec0: S=U1+(2Bh+B2)U2/3 ; sec1: A_h U2/3 ; sec2: A2 U2/3 (-> W' bf16)
// sec3: Cf=(B2-Bh)U2/6 (fp32). cb==8: bias folding.
__global__ __launch_bounds__(256, 2) void gemm_pre(const float* __restrict__ msg_w,
                                                   const float* __restrict__ upd_w,
                                                   const float* __restrict__ msg_b,
                                                   const float* __restrict__ upd_b) {
    int cb = blockIdx.x, rb = blockIdx.y, lh = blockIdx.z;
    int l = lh >> 1, h = lh & 1;

    __shared__ float As[2][16][132];
    __shared__ float Bs[2][16][128];
    int tid = threadIdx.x;

    if (cb == 8) {
        if (rb != 0) return;
        float* v1 = &As[0][0][0];
        float* v2 = v1 + HD;
        int c = tid;
        float mbh = msg_b[(l*3 + h)*HD + c];
        float mb2 = msg_b[(l*3 + 2)*HD + c];
        v1[c] = 2.f*mbh + mb2;
        v2[c] = mbh + mb2;
        __syncthreads();
        const float* U2 = upd_w + ((size_t)l*512 + HD) * HD;
        float s1 = 0.f, s2 = 0.f;
        for (int k = 0; k < HD; k++) {
            float u = U2[(size_t)k*HD + c];
            s1 += v1[k]*u; s2 += v2[k]*u;
        }
        g_bias [lh*HD + c] = s1*(1.f/3.f) + upd_b[l*HD + c];
        g_bias2[lh*HD + c] = s2*0.5f     + upd_b[l*HD + c];
        return;
    }

    int sec = cb >> 1;
    int col0 = (cb & 1) * 128;
    int row0 = rb * 128;
    const float* mh = msg_w + (size_t)(l*3 + h) * 512 * HD;
    const float* m2 = msg_w + (size_t)(l*3 + 2) * 512 * HD;
    const float* U1 = upd_w + (size_t)l * 512 * HD;
    const float* U2 = U1 + (size_t)HD * HD;
    const float* P1; const float* P2; float w1, w2, scale; int addU1;
    if (sec == 0)      { P1 = mh + HD*HD; w1 = 2.f; P2 = m2 + HD*HD; w2 = 1.f;  scale = 1.f/3.f; addU1 = 1; }
    else if (sec == 1) { P1 = mh;          w1 = 1.f; P2 = 0;          w2 = 0.f;  scale = 1.f/3.f; addU1 = 0; }
    else if (sec == 2) { P1 = m2;          w1 = 1.f; P2 = 0;          w2 = 0.f;  scale = 1.f/3.f; addU1 = 0; }
    else               { P1 = m2 + HD*HD; w1 = 1.f; P2 = mh + HD*HD; w2 = -1.f; scale = 1.f/6.f; addU1 = 0; }

    int tx = tid & 15, ty = tid >> 4;
    int ar = tid >> 2, ak = (tid & 3) * 4;
    int bk = tid >> 5, bn = (tid & 31) * 4;

    float acc[8][8];
    #pragma unroll
    for (int i = 0; i < 8; i++)
        #pragma unroll
        for (int j = 0; j < 8; j++) acc[i][j] = 0.f;

    float4 a0v, a1v, b0v, b1v;
    {
        int r0 = row0 + ar, r1 = row0 + ar + 64;
        a0v = ld4(&P1[(size_t)r0*HD + ak]);
        a1v = ld4(&P1[(size_t)r1*HD + ak]);
        if (P2) { a0v = f4fma(w2/w1, ld4(&P2[(size_t)r0*HD + ak]), a0v);
                  a1v = f4fma(w2/w1, ld4(&P2[(size_t)r1*HD + ak]), a1v); }
        b0v = ld4(&U2[(size_t)bk*HD + col0 + bn]);
        b1v = ld4(&U2[(size_t)(bk+8)*HD + col0 + bn]);
    }
    As[0][ak+0][ar]=a0v.x; As[0][ak+1][ar]=a0v.y; As[0][ak+2][ar]=a0v.z; As[0][ak+3][ar]=a0v.w;
    As[0][ak+0][64+ar]=a1v.x; As[0][ak+1][64+ar]=a1v.y; As[0][ak+2][64+ar]=a1v.z; As[0][ak+3][64+ar]=a1v.w;
    *(float4*)&Bs[0][bk][bn] = b0v; *(float4*)&Bs[0][bk+8][bn] = b1v;
    __syncthreads();

    int buf = 0;
    #pragma unroll 1
    for (int t = 0; t < 16; t++) {
        if (t < 15) {
            int k0 = (t + 1) * 16;
            int r0 = row0 + ar, r1 = row0 + ar + 64;
            a0v = ld4(&P1[(size_t)r0*HD + k0 + ak]);
            a1v = ld4(&P1[(size_t)r1*HD + k0 + ak]);
            if (P2) { a0v = f4fma(w2/w1, ld4(&P2[(size_t)r0*HD + k0 + ak]), a0v);
                      a1v = f4fma(w2/w1, ld4(&P2[(size_t)r1*HD + k0 + ak]), a1v); }
            b0v = ld4(&U2[(size_t)(k0+bk)*HD + col0 + bn]);
            b1v = ld4(&U2[(size_t)(k0+bk+8)*HD + col0 + bn]);
        }
        #pragma unroll
        for (int k = 0; k < 16; k++) {
            float4 pa0 = *(float4*)&As[buf][k][ty*4];
            float4 pa1 = *(float4*)&As[buf][k][64 + ty*4];
            float4 pb0 = *(float4*)&Bs[buf][k][tx*4];
            float4 pb1 = *(float4*)&Bs[buf][k][64 + tx*4];
            float aa[8] = {pa0.x,pa0.y,pa0.z,pa0.w,pa1.x,pa1.y,pa1.z,pa1.w};
            float bb[8] = {pb0.x,pb0.y,pb0.z,pb0.w,pb1.x,pb1.y,pb1.z,pb1.w};
            #pragma unroll
            for (int i = 0; i < 8; i++)
                #pragma unroll
                for (int j = 0; j < 8; j++)
                    acc[i][j] = fmaf(aa[i], bb[j], acc[i][j]);
        }
        if (t < 15) {
            int nb2 = buf ^ 1;
            As[nb2][ak+0][ar]=a0v.x; As[nb2][ak+1][ar]=a0v.y; As[nb2][ak+2][ar]=a0v.z; As[nb2][ak+3][ar]=a0v.w;
            As[nb2][ak+0][64+ar]=a1v.x; As[nb2][ak+1][64+ar]=a1v.y; As[nb2][ak+2][64+ar]=a1v.z; As[nb2][ak+3][64+ar]=a1v.w;
            *(float4*)&Bs[nb2][bk][bn] = b0v; *(float4*)&Bs[nb2][bk+8][bn] = b1v;
        }
        __syncthreads();
        buf ^= 1;
    }

    float sc = w1 * scale;
    #pragma unroll
    for (int ih = 0; ih < 2; ih++)
        #pragma unroll
        for (int ii = 0; ii < 4; ii++) {
            int r = row0 + ih*64 + ty*4 + ii;          // k index (0..255)
            #pragma unroll
            for (int jh = 0; jh < 2; jh++) {
                int c = col0 + jh*64 + tx*4;           // n index (0..255)
                float vv[4];
                #pragma unroll
                for (int j = 0; j < 4; j++) vv[j] = acc[ih*4+ii][jh*4+j] * sc;
                if (addU1) {
                    float4 u = ld4(&U1[(size_t)r*HD + c]);
                    vv[0]+=u.x; vv[1]+=u.y; vv[2]+=u.z; vv[3]+=u.w;
                }
                if (sec < 3) {
                    #pragma unroll
                    for (int j = 0; j < 4; j++) {
                        size_t o = ((size_t)lh*HD + (c + j))*KTOT + sec*HD + r;
                        __nv_bfloat16 hi = __float2bfloat16(vv[j]);
                        g_wth[o] = hi;
                        g_wtl[o] = __float2bfloat16(vv[j] - __bfloat162float(hi));
                    }
                } else {
                    float4 v = make_float4(vv[0],vv[1],vv[2],vv[3]);
                    *(float4*)&g_Cf[(size_t)lh*HD*HD + (size_t)r*HD + c] = v;
                }
            }
        }
}

// ---------------- buildY: only sec1 = x(n-1)+x(n+1) (1.5x at endpoints) --
__global__ __launch_bounds__(256) void buildY() {
    int node = blockIdx.x * 8 + (threadIdx.x >> 5);
    int lane = threadIdx.x & 31;
    int half = node >= NB ? 1 : 0;
    int i = node - half * NB;
    int c = lane * 8;
    float f[8] = {0.f,0.f,0.f,0.f,0.f,0.f,0.f,0.f};
    if (i > 0) {
        float a[8]; unpack8(*(const uint4*)&g_xh[(size_t)(node-1)*HD + c], a);
        #pragma unroll
        for (int j = 0; j < 8; j++) f[j] += a[j];
    }
    if (i < NB - 1) {
        float a[8]; unpack8(*(const uint4*)&g_xh[(size_t)(node+1)*HD + c], a);
        #pragma unroll
        for (int j = 0; j < 8; j++) f[j] += a[j];
    }
    if (i == 0 || i == NB - 1) {
        #pragma unroll
        for (int j = 0; j < 8; j++) f[j] *= 1.5f;
    }
    *(uint4*)&g_Y[(size_t)node*KTOT + 256 + c] = pack8(f);
}

// ---------------- tensor-core GEMM: u = Y @ W'^T (tile 128x64, 3 CTA/SM) -
#define A_SZ    10240            // 128 rows * 80 B
#define BH_SZ   5120             // 64 rows * 80 B
#define STG_TOT 20480            // A | BH | BL
#define SMEM_MMA 40960           // 2 stages (C stage 128*68*4=34816 fits)

__global__ __launch_bounds__(256, 3) void gemm_mma(int l) {
    extern __shared__ __align__(16) char sm[];
    uint32_t sb = smem_u32(sm);
    int tid = threadIdx.x, wid = tid >> 5, lane = tid & 31;
    int cb = blockIdx.x, rb = blockIdx.y, half = blockIdx.z;
    int lh = l*2 + half;
    const __nv_bfloat16* Bwh = g_wth + (size_t)lh*HD*KTOT;
    const __nv_bfloat16* Bwl = g_wtl + (size_t)lh*HD*KTOT;

    int lr0 = tid >> 2, lseg = tid & 3;
    int r0 = rb*128 + lr0;      if (r0 >= NB) r0 = NB-1;
    int r1 = rb*128 + lr0 + 64; if (r1 >= NB) r1 = NB-1;
    size_t an0 = (size_t)(half*NB + r0) * KTOT;
    size_t an1 = (size_t)(half*NB + r1) * KTOT;
    size_t bn0 = (size_t)(cb*64 + lr0) * KTOT;   // B row lr0 (0..63)

    #define LOAD_STAGE(s, k0) do {                                             \
        uint32_t d0 = sb + (uint32_t)(s)*STG_TOT + lr0*80 + lseg*16;           \
        size_t ka = (size_t)(k0) + lseg*8;                                     \
        cpa16(d0,          g_Y + an0 + ka);                                    \
        cpa16(d0 + 64*80,  g_Y + an1 + ka);                                    \
        cpa16(d0 + A_SZ,          Bwh + bn0 + ka);                             \
        cpa16(d0 + A_SZ + BH_SZ,  Bwl + bn0 + ka);                             \
        asm volatile("cp.async.commit_group;" ::: "memory");                   \
    } while (0)

    float acc[2][4][4];
    #pragma unroll
    for (int i = 0; i < 2; i++)
        #pragma unroll
        for (int j = 0; j < 4; j++)
            #pragma unroll
            for (int q = 0; q < 4; q++) acc[i][j][q] = 0.f;

    LOAD_STAGE(0, 0);
    LOAD_STAGE(1, 32);

    int warp_m = (wid >> 1) * 32, warp_n = (wid & 1) * 32;
    int la7 = lane & 7, lb8 = (lane >> 3) & 1, lhi = lane >> 4;
    uint32_t aoff = (uint32_t)(warp_m + la7 + lb8*8)*80 + lhi*16;
    uint32_t boff = A_SZ + (uint32_t)(warp_n + lhi*8 + la7)*80 + lb8*16;

    #pragma unroll 1
    for (int kt = 0; kt < 24; kt++) {
        if (kt < 23) asm volatile("cp.async.wait_group 1;" ::: "memory");
        else         asm volatile("cp.async.wait_group 0;" ::: "memory");
        __syncthreads();
        uint32_t stg = sb + (uint32_t)(kt & 1) * STG_TOT;
        #pragma unroll
        for (int k16 = 0; k16 < 2; k16++) {
            uint32_t ko = k16 * 32;
            uint32_t ah[2][4];
            #pragma unroll
            for (int i = 0; i < 2; i++)
                LDM4(ah[i], stg + aoff + i*1280 + ko);
            #pragma unroll
            for (int jj = 0; jj < 2; jj++) {
                uint32_t bh[4], bl[4];
                LDM4(bh, stg + boff + jj*1280 + ko);
                LDM4(bl, stg + BH_SZ + boff + jj*1280 + ko);
                #pragma unroll
                for (int j2 = 0; j2 < 2; j2++) {
                    int j = jj*2 + j2;
                    #pragma unroll
                    for (int i = 0; i < 2; i++) {
                        MMA2(acc[i][j], ah[i], bh[j2*2], bh[j2*2+1]);
                        MMA2(acc[i][j], ah[i], bl[j2*2], bl[j2*2+1]);
                    }
                }
            }
        }
        __syncthreads();
        if (kt + 2 < 24) LOAD_STAGE(kt & 1, (kt + 2) * 32);
    }

    asm volatile("cp.async.wait_group 0;" ::: "memory");
    __syncthreads();
    float* Cs = (float*)sm;                    // 128 x 68 floats
    int g = lane >> 2;
    int ct = (lane & 3) * 2;
    #pragma unroll
    for (int i = 0; i < 2; i++)
        #pragma unroll
        for (int j = 0; j < 4; j++) {
            int r = warp_m + i*16 + g;
            int c = warp_n + j*8 + ct;
            *(float2*)&Cs[(size_t)r*68 + c]      = make_float2(acc[i][j][0], acc[i][j][1]);
            *(float2*)&Cs[(size_t)(r+8)*68 + c]  = make_float2(acc[i][j][2], acc[i][j][3]);
        }
    __syncthreads();
    #pragma unroll
    for (int it = 0; it < 8; it++) {
        int idx = tid + it*256;                // 2048 = 128 rows x 16 float4
        int r = idx >> 4, c4 = (idx & 15) * 4;
        int node = rb*128 + r;
        if (node < NB) {
            float4 v = *(float4*)&Cs[(size_t)r*68 + c4];
            uint2 pk;
            pk.x = pk2(v.x, v.y); pk.y = pk2(v.z, v.w);
            *(uint2*)&g_U[((size_t)(half*NB + node))*HD + cb*64 + c4] = pk;
        }
    }
    #undef LOAD_STAGE
}

// ---------------- ep_fix: g_U[endpoint] += Cf@x + (bias2 - bias) ---------
__global__ void ep_fix(int l) {
    int e  = blockIdx.x >> 3;
    int cc = blockIdx.x & 7;
    int half = e >> 1;
    int i = (e & 1) ? NB - 1 : 0;
    int node = half * NB + i;
    int lh = l*2 + half;
    int tid = threadIdx.x;
    int col = cc*32 + (tid & 31);
    int kg  = tid >> 5;

    __shared__ float xs[HD];
    __shared__ float red[8][33];
    xs[tid] = __bfloat162float(g_xh[(size_t)node*HD + tid]);
    __syncthreads();

    const float* Cf = g_Cf + (size_t)lh*HD*HD;
    float p = 0.f;
    #pragma unroll 8
    for (int k = kg*32; k < kg*32 + 32; k++)
        p = fmaf(xs[k], Cf[(size_t)k*HD + col], p);
    red[kg][tid & 31] = p;
    __syncthreads();
    if (kg == 0) {
        float s = 0.f;
        #pragma unroll
        for (int w = 0; w < 8; w++) s += red[w][tid & 31];
        size_t o = (size_t)node*HD + col;
        float u = __bfloat162float(g_U[o]) + s
                + g_bias2[lh*HD + col] - g_bias[lh*HD + col];
        g_U[o] = __float2bfloat16(u);
    }
}

// ---------------- combine2: LN + GeLU + residual + Y scatter -------------
__global__ __launch_bounds__(256) void combine2(int l,
        const float* __restrict__ ln_g, const float* __restrict__ ln_b) {
    int node = blockIdx.x * 8 + (threadIdx.x >> 5);
    int lane = threadIdx.x & 31;
    int half = node >= NB ? 1 : 0;
    int i = node - half * NB;
    int p = half ? node - NB : node + NB;
    int c = lane * 8;

    float u[8];
    unpack8(*(const uint4*)&g_U[(size_t)node*HD + c], u);
    const float* bi = g_bias + (l*2 + half) * HD;
    float4 bi0 = ld4(bi + c), bi1 = ld4(bi + c + 4);
    u[0]+=bi0.x; u[1]+=bi0.y; u[2]+=bi0.z; u[3]+=bi0.w;
    u[4]+=bi1.x; u[5]+=bi1.y; u[6]+=bi1.z; u[7]+=bi1.w;

    float s = 0.f, q = 0.f;
    #pragma unroll
    for (int j = 0; j < 8; j++) { s += u[j]; q = fmaf(u[j], u[j], q); }
    #pragma unroll
    for (int off = 16; off; off >>= 1) {
        s += __shfl_xor_sync(0xffffffff, s, off);
        q += __shfl_xor_sync(0xffffffff, q, off);
    }
    float mu = s * (1.f/HD);
    float rs = rsqrtf(q * (1.f/HD) - mu*mu + 1e-5f);

    float4 g0 = ld4(ln_g + l*HD + c), g1 = ld4(ln_g + l*HD + c + 4);
    float4 b0 = ld4(ln_b + l*HD + c), b1 = ld4(ln_b + l*HD + c + 4);
    float gg[8] = {g0.x,g0.y,g0.z,g0.w,g1.x,g1.y,g1.z,g1.w};
    float bb[8] = {b0.x,b0.y,b0.z,b0.w,b1.x,b1.y,b1.z,b1.w};

    float x8[8];
    unpack8(*(const uint4*)&g_xh[(size_t)node*HD + c], x8);
    #pragma unroll
    for (int j = 0; j < 8; j++)
        x8[j] += gelu_exact((u[j] - mu) * rs * gg[j] + bb[j]);
    uint4 pk = pack8(x8);
    *(uint4*)&g_xh[(size_t)node*HD + c] = pk;
    *(uint4*)&g_Y[(size_t)node*KTOT + c] = pk;              // sec0
    uint4 pk2v = pk;
    if (i == 0 || i == NB - 1) {
        float sx[8];
        #pragma unroll
        for (int j = 0; j < 8; j++) sx[j] = x8[j] * 1.5f;
        pk2v = pack8(sx);
    }
    *(uint4*)&g_Y[(size_t)p*KTOT + 512 + c] = pk2v;         // sec2 of partner
}

// ---------------- readout ----------------
__global__ void colmean() {
    int c = threadIdx.x;
    int r0 = blockIdx.x * 100;
    float s = 0.f;
    for (int r = r0; r < r0 + 100; r++)
        s += __bfloat162float(g_xh[(size_t)r * HD + c]);
    g_part[blockIdx.x * HD + c] = s;
}

__global__ void decoder(const float* __restrict__ dec1_w, const float* __restrict__ dec1_b,
                        const float* __restrict__ dec2_w, const float* __restrict__ dec2_b,
                        const float* __restrict__ Kp, const float* __restrict__ tau,
                        const float* __restrict__ tau_max, const float* __restrict__ lam,
                        float* __restrict__ out) {
    __shared__ float hm[HD], z[HD], red[64];
    int t = threadIdx.x;
    float acc0 = 0.f;
    for (int b = 0; b < 200; b++) acc0 += g_part[b * HD + t];
    hm[t] = acc0 * (1.0f / NB);
    __syncthreads();
    float acc = dec1_b[t];
    for (int k = 0; k < HD; k++) acc += hm[k] * dec1_w[k * HD + t];
    z[t] = gelu_exact(acc);
    __syncthreads();
    if (t < 128) {
        float a = dec2_b[t];
        for (int k = 0; k < HD; k++) a += z[k] * dec2_w[k * 128 + t];
        out[t] = a;
    }
    if (t < 64) {
        red[t] = Kp[t] * tau[t] / tau_max[t];
        out[129 + t] = Kp[t];
    }
    __syncthreads();
    if (t == 0) {
        float s = 0.f;
        for (int i = 0; i < 64; i++) s += red[i];
        out[128] = fabsf(lam[0]) - s;
    }
}

// ---------------- launch ----------------
extern "C" void kernel_launch(void* const* d_in, const int* in_sizes, int n_in,
                              void* d_out, int out_size) {
    const float* energy_x     = (const float*)d_in[0];
    const float* comm_x       = (const float*)d_in[1];
    const float* tau          = (const float*)d_in[2];
    const float* tau_max      = (const float*)d_in[3];
    const float* lambda_min_0 = (const float*)d_in[4];
    const float* We_w         = (const float*)d_in[5];
    const float* We_b         = (const float*)d_in[6];
    const float* Wc_w         = (const float*)d_in[7];
    const float* Wc_b         = (const float*)d_in[8];
    const float* msg_w        = (const float*)d_in[9];
    const float* msg_b        = (const float*)d_in[10];
    const float* upd_w        = (const float*)d_in[11];
    const float* upd_b        = (const float*)d_in[12];
    const float* ln_g         = (const float*)d_in[13];
    const float* ln_b         = (const float*)d_in[14];
    const float* dec1_w       = (const float*)d_in[15];
    const float* dec1_b       = (const float*)d_in[16];
    const float* dec2_w       = (const float*)d_in[17];
    const float* dec2_b       = (const float*)d_in[18];
    const float* K_param      = (const float*)d_in[19];
    float* out = (float*)d_out;

    cudaFuncSetAttribute(gemm_mma, cudaFuncAttributeMaxDynamicSharedMemorySize, SMEM_MMA);

    gemm_pre<<<dim3(9, 2, 8), 256>>>(msg_w, upd_w, msg_b, upd_b);
    encode<<<(TWO_N * HD / 8 + 255) / 256, 256>>>(energy_x, comm_x, We_w, We_b, Wc_w, Wc_b);

    for (int l = 0; l < NL; l++) {
        buildY<<<TWO_N / 8, 256>>>();
        gemm_mma<<<dim3(4, (NB + 127) / 128, 2), 256, SMEM_MMA>>>(l);
        ep_fix<<<32, 256>>>(l);
        combine2<<<TWO_N / 8, 256>>>(l, ln_g, ln_b);
    }

    colmean<<<200, 256>>>();
    decoder<<<1, 256>>>(dec1_w, dec1_b, dec2_w, dec2_b,
                        K_param, tau, tau_max, lambda_min_0, out);
}